// round 8
// baseline (speedup 1.0000x reference)
#include <cuda_runtime.h>
#include <math.h>
#include <stdint.h>

#define BB 8
#define LL 2048
#define DM 512
#define DI 1024
#define NH 16
#define HD 64
#define CD 1056
#define DIP 2096
#define MT (BB*LL)      // 16384 tokens
#define CL 128          // scan chunk length
#define NC (LL/CL)      // 16 chunks
#define NSCAN 256       // 2 dirs * 8 batch * 16 heads

// ---------------- scratch (static device globals; no allocation) ----------------
__device__ float g_zx [2ull*MT*DIP];
__device__ float g_xbc[2ull*MT*CD];
__device__ float g_dt [2ull*MT*NH];
__device__ float g_dA [2ull*MT*NH];
__device__ float g_y  [2ull*MT*DI];
__device__ float g_g  [2ull*MT*DI];
__device__ float g_P  [(size_t)NSCAN*LL];
__device__ float g_S  [(size_t)NSCAN*NC*HD*16];
__device__ float g_hin[(size_t)NSCAN*NC*HD*16];

__device__ __forceinline__ float siluf(float v)     { return v / (1.f + expf(-v)); }
__device__ __forceinline__ float softplusf(float v) { return fmaxf(v, 0.f) + log1pf(expf(-fabsf(v))); }
__device__ __forceinline__ uint32_t f2tf32(float f) {
    uint32_t r; asm("cvt.rna.tf32.f32 %0, %1;" : "=r"(r) : "f"(f)); return r;
}
__device__ __forceinline__ void mma8(float* c, const uint32_t* a, const uint32_t* b) {
    asm volatile(
        "mma.sync.aligned.m16n8k8.row.col.f32.tf32.tf32.f32 "
        "{%0,%1,%2,%3}, {%4,%5,%6,%7}, {%8,%9}, {%0,%1,%2,%3};"
        : "+f"(c[0]), "+f"(c[1]), "+f"(c[2]), "+f"(c[3])
        : "r"(a[0]), "r"(a[1]), "r"(a[2]), "r"(a[3]), "r"(b[0]), "r"(b[1]));
}
__device__ __forceinline__ void cpa16(const void* sp, const void* g) {
    uint32_t s = (uint32_t)__cvta_generic_to_shared(sp);
    asm volatile("cp.async.cg.shared.global [%0], [%1], 16;" :: "r"(s), "l"(g));
}
__device__ __forceinline__ void cpa16p(const void* sp, const void* g, bool pred) {
    uint32_t s = (uint32_t)__cvta_generic_to_shared(sp);
    int sz = pred ? 16 : 0;
    asm volatile("cp.async.cg.shared.global [%0], [%1], 16, %2;" :: "r"(s), "l"(g), "r"(sz));
}
__device__ __forceinline__ void cpa4(const void* sp, const void* g) {
    uint32_t s = (uint32_t)__cvta_generic_to_shared(sp);
    asm volatile("cp.async.ca.shared.global [%0], [%1], 4;" :: "r"(s), "l"(g));
}
#define CP_COMMIT() asm volatile("cp.async.commit_group;" ::: "memory")
#define CP_WAIT(n)  asm volatile("cp.async.wait_group %0;" :: "n"(n) : "memory")

// ============================================================================
// GEMM (BM=128, BN=256, BK=32; 8 warps 2m x 4n, warp tile 64x64), 2-stage.
// smem [row][36] floats: conflict-free fragment reads.
// Dynamic smem: 2*(128+256)*36*4 = 110592 B -> 1 CTA/SM.
// ============================================================================
#define GEMM_SMEM 110592
#define ASM(st,r,k) sA[((st)*128 + (r))*36 + (k)]
#define BSM(st,r,k) sB[((st)*256 + (r))*36 + (k)]

#define GEMM_PROLOGUE \
    extern __shared__ float smp[]; \
    float* sA = smp; \
    float* sB = smp + 2*128*36; \
    const int tid  = threadIdx.x; \
    const int lane = tid & 31; \
    const int wid  = tid >> 5; \
    const int mw   = wid & 1; \
    const int nw   = wid >> 1; \
    const int g = lane >> 2; \
    const int q = lane & 3; \
    float acc[4][8][4]; \
    _Pragma("unroll") for (int i = 0; i < 4; i++) \
    _Pragma("unroll") for (int j = 0; j < 8; j++) \
    _Pragma("unroll") for (int r = 0; r < 4; r++) acc[i][j][r] = 0.f;

#define GEMM_COMPUTE(cur) \
    _Pragma("unroll") \
    for (int kk = 0; kk < 32; kk += 8) { \
        uint32_t af[4][4], bf[8][2]; \
        _Pragma("unroll") \
        for (int mt = 0; mt < 4; mt++) { \
            int row = mw * 64 + mt * 16 + g; \
            af[mt][0] = f2tf32(ASM(cur, row    , kk + q    )); \
            af[mt][1] = f2tf32(ASM(cur, row + 8, kk + q    )); \
            af[mt][2] = f2tf32(ASM(cur, row    , kk + q + 4)); \
            af[mt][3] = f2tf32(ASM(cur, row + 8, kk + q + 4)); \
        } \
        _Pragma("unroll") \
        for (int nt = 0; nt < 8; nt++) { \
            int col = nw * 64 + nt * 8 + g; \
            bf[nt][0] = f2tf32(BSM(cur, col, kk + q    )); \
            bf[nt][1] = f2tf32(BSM(cur, col, kk + q + 4)); \
        } \
        _Pragma("unroll") \
        for (int mt = 0; mt < 4; mt++) \
        _Pragma("unroll") \
        for (int nt = 0; nt < 8; nt++) \
            mma8(acc[mt][nt], af[mt], bf[nt]); \
    }

#define GEMM_MAINLOOP(T) \
    load_tile(0, 0); CP_COMMIT(); \
    load_tile(1, 1); CP_COMMIT(); \
    for (int kt = 0; kt < (T); kt++) { \
        const int cur = kt & 1; \
        if (kt + 1 < (T)) { CP_WAIT(1); } else { CP_WAIT(0); } \
        __syncthreads(); \
        GEMM_COMPUTE(cur) \
        __syncthreads(); \
        if (kt + 2 < (T)) { load_tile(kt + 2, cur); CP_COMMIT(); } \
    }

// ---------------- in_proj: grid (9,128,2); z selects direction ----------------
__global__ void __launch_bounds__(256, 1)
gemm_in(const float* __restrict__ A, const float* __restrict__ B0,
        const float* __restrict__ B1, float* __restrict__ Cb)
{
    const float* B = blockIdx.z ? B1 : B0;
    float* C = Cb + (size_t)blockIdx.z * MT * DIP;
    const int m0 = blockIdx.y * 128, n0 = blockIdx.x * 256;
    const int N = DIP, K = DM;

    GEMM_PROLOGUE

    auto load_tile = [&](int kt, int buf) {
        const int k0 = kt << 5;
#pragma unroll
        for (int i = 0; i < 4; i++) {
            int id  = tid + (i << 8);
            int row = id >> 3;
            int ce  = (id & 7) << 2;
            cpa16(&ASM(buf, row, ce), A + (size_t)(m0 + row) * K + k0 + ce);
        }
#pragma unroll
        for (int i = 0; i < 8; i++) {
            int id  = tid + (i << 8);
            int row = id >> 3;
            int ce  = (id & 7) << 2;
            cpa16p(&BSM(buf, row, ce), B + (size_t)(n0 + row) * K + k0 + ce,
                   (n0 + row) < N);
        }
    };

    GEMM_MAINLOOP(K >> 5)

#pragma unroll
    for (int mt = 0; mt < 4; mt++) {
        int row = m0 + mw * 64 + mt * 16 + g;
#pragma unroll
        for (int nt = 0; nt < 8; nt++) {
            int n = n0 + nw * 64 + nt * 8 + q * 2;
            if (n < N) {
                *(float2*)(C + (size_t)row * DIP + n) =
                    make_float2(acc[mt][nt][0], acc[mt][nt][1]);
                *(float2*)(C + (size_t)(row + 8) * DIP + n) =
                    make_float2(acc[mt][nt][2], acc[mt][nt][3]);
            }
        }
    }
}

// ---------------- out_proj: K-concat of fwd+bwd (K=2048) -> single write ----------------
__global__ void __launch_bounds__(256, 1)
gemm_out(const float* __restrict__ A0, const float* __restrict__ A1,
         const float* __restrict__ B0, const float* __restrict__ B1,
         float* __restrict__ C)
{
    const int m0 = blockIdx.y * 128, n0 = blockIdx.x * 256;
    const int K = 2 * DI;

    GEMM_PROLOGUE

    auto load_tile = [&](int kt, int buf) {
        const int k0 = kt << 5;
        const float* Ap; const float* Bp; int kl;
        if (k0 < DI) { Ap = A0; Bp = B0; kl = k0; }
        else         { Ap = A1; Bp = B1; kl = k0 - DI; }
#pragma unroll
        for (int i = 0; i < 4; i++) {
            int id  = tid + (i << 8);
            int row = id >> 3;
            int ce  = (id & 7) << 2;
            cpa16(&ASM(buf, row, ce), Ap + (size_t)(m0 + row) * DI + kl + ce);
        }
#pragma unroll
        for (int i = 0; i < 8; i++) {
            int id  = tid + (i << 8);
            int row = id >> 3;
            int ce  = (id & 7) << 2;
            cpa16(&BSM(buf, row, ce), Bp + (size_t)(n0 + row) * DI + kl + ce);
        }
    };

    GEMM_MAINLOOP(K >> 5)

#pragma unroll
    for (int mt = 0; mt < 4; mt++) {
        int row = m0 + mw * 64 + mt * 16 + g;
#pragma unroll
        for (int nt = 0; nt < 8; nt++) {
            int n = n0 + nw * 64 + nt * 8 + q * 2;
            *(float2*)(C + (size_t)row * DM + n) =
                make_float2(acc[mt][nt][0], acc[mt][nt][1]);
            *(float2*)(C + (size_t)(row + 8) * DM + n) =
                make_float2(acc[mt][nt][2], acc[mt][nt][3]);
        }
    }
}

// ---------------- depthwise conv(4) + bias + SiLU, 8 outputs per thread ----------------
#define CTT 8
__global__ __launch_bounds__(256)
void conv_silu_k(const float* __restrict__ cwF, const float* __restrict__ cbF,
                 const float* __restrict__ cwB, const float* __restrict__ cbB)
{
    long idx = (long)blockIdx.x * 256 + threadIdx.x;
    int  c  = (int)(idx % CD);
    long q2 = idx / CD;
    int  tg = (int)(q2 & (LL / CTT - 1));
    int  bd = (int)(q2 >> 8);
    int  b  = bd & 7, d = bd >> 3;
    int  t0 = tg * CTT;

    const float* wv = (d == 0 ? cwF : cwB) + c * 4;
    float w0 = wv[0], w1 = wv[1], w2 = wv[2], w3 = wv[3];
    float bias = (d == 0 ? cbF : cbB)[c];
    long rbase = (long)d * MT + (long)b * LL;
    const float* zin = g_zx + rbase * (long)DIP + DI + c;
    float* outp = g_xbc + (rbase + t0) * (long)CD + c;

    float in[CTT + 3];
    if (d == 0) {
#pragma unroll
        for (int j = 0; j < CTT + 3; j++) {
            int tt = t0 - 3 + j;
            in[j] = (tt >= 0) ? zin[(long)tt * DIP] : 0.f;
        }
#pragma unroll
        for (int i = 0; i < CTT; i++) {
            float a = bias;
            a = fmaf(w0, in[i], a); a = fmaf(w1, in[i+1], a);
            a = fmaf(w2, in[i+2], a); a = fmaf(w3, in[i+3], a);
            outp[(long)i * CD] = siluf(a);
        }
    } else {
#pragma unroll
        for (int j = 0; j < CTT + 3; j++) {
            int tt = t0 + j;
            in[j] = (tt < LL) ? zin[(long)tt * DIP] : 0.f;
        }
#pragma unroll
        for (int i = 0; i < CTT; i++) {
            float a = bias;
            a = fmaf(w3, in[i], a); a = fmaf(w2, in[i+1], a);
            a = fmaf(w1, in[i+2], a); a = fmaf(w0, in[i+3], a);
            outp[(long)i * CD] = siluf(a);
        }
    }
}

// ---------------- dt exact fp32, W cached in smem; 64 tokens per block ----------------
__global__ __launch_bounds__(256)
void dadt_k(const float* __restrict__ x,
            const float* __restrict__ ipwF, const float* __restrict__ ipwB,
            const float* __restrict__ dbF,  const float* __restrict__ alF,
            const float* __restrict__ dbB,  const float* __restrict__ alB)
{
    __shared__ float sW[16][512];
    int blk = blockIdx.x;
    int d   = blk >> 8;
    int tb  = blk & 255;
    int tid = threadIdx.x;

    const float* W = (d ? ipwB : ipwF) + (size_t)(DI + CD) * DM;
#pragma unroll
    for (int j = 0; j < 8; j++)
        ((float4*)&sW[0][0])[j * 256 + tid] = ((const float4*)W)[j * 256 + tid];
    __syncthreads();

    int h = tid >> 4, l = tid & 15;
    float db = (d ? dbB : dbF)[h];
    float A  = -expf((d ? alB : alF)[h]);

    for (int tk = 0; tk < 64; tk++) {
        int token = tb * 64 + tk;
        const float4* xr = (const float4*)(x + (size_t)token * DM);
        const float4* wr = (const float4*)&sW[h][0];
        float s = 0.f;
#pragma unroll
        for (int j = 0; j < 8; j++) {
            float4 xv = xr[l + 16 * j];
            float4 wv = wr[l + 16 * j];
            s = fmaf(xv.x, wv.x, s); s = fmaf(xv.y, wv.y, s);
            s = fmaf(xv.z, wv.z, s); s = fmaf(xv.w, wv.w, s);
        }
        s += __shfl_xor_sync(~0u, s, 1);
        s += __shfl_xor_sync(~0u, s, 2);
        s += __shfl_xor_sync(~0u, s, 4);
        s += __shfl_xor_sync(~0u, s, 8);
        if (l == 0) {
            float dt = softplusf(s + db);
            size_t r = (size_t)d * MT + token;
            g_dt[r * NH + h] = dt;
            g_dA[r * NH + h] = expf(dt * A);
        }
    }
}

// ---------------- scan pass 1: chunk scans, cp.async smem double-buffer ----------------
__global__ __launch_bounds__(64)
void chunk_scan_k(const float* __restrict__ DpF, const float* __restrict__ DpB)
{
    int blk = blockIdx.x;
    int c   = blk & (NC - 1);
    int sid = blk >> 4;
    int d = sid >> 7, b = (sid >> 4) & 7, h = sid & 15;
    int p = threadIdx.x;

    __shared__ float sBC[2][8][36];   // [buf][j][B16,C16,dt,dA,pad]
    __shared__ float sX [2][8][64];   // [buf][j][p]
    float hs[16];
#pragma unroll
    for (int n = 0; n < 16; n++) hs[n] = 0.f;
    float dp = (d == 0 ? DpF : DpB)[h];
    long base0 = (long)d * MT + (long)b * LL;
    int s0 = c * CL;

    auto rowof = [&](int s) -> long {
        int t = (d == 0) ? s : (LL - 1 - s);
        return base0 + t;
    };
    auto loadgrp = [&](int gg, int buf) {
        // B/C: 8 rows x 32 floats = 64 x 16B segments, one per thread
        {
            int j = p >> 3, seg = p & 7;
            long row = rowof(s0 + gg * 8 + j);
            cpa16(&sBC[buf][j][seg * 4], &g_xbc[row * (long)CD + DI + seg * 4]);
        }
        // x: 8 rows x 64 floats = 128 x 16B segments, two per thread
#pragma unroll
        for (int it = 0; it < 2; it++) {
            int idx = p + it * 64;
            int j = idx >> 4, c4 = (idx & 15) << 2;
            long row = rowof(s0 + gg * 8 + j);
            cpa16(&sX[buf][j][c4], &g_xbc[row * (long)CD + h * HD + c4]);
        }
        // dt / dA: one 4B cp per row
        if (p < 8) {
            long row = rowof(s0 + gg * 8 + p);
            cpa4(&sBC[buf][p][32], &g_dt[row * (long)NH + h]);
        } else if (p < 16) {
            long row = rowof(s0 + gg * 8 + (p - 8));
            cpa4(&sBC[buf][p - 8][33], &g_dA[row * (long)NH + h]);
        }
    };

    loadgrp(0, 0);
    CP_COMMIT();

    float P = 1.f;
    for (int gg = 0; gg < 16; gg++) {
        int buf = gg & 1;
        if (gg + 1 < 16) {
            loadgrp(gg + 1, buf ^ 1);
            CP_COMMIT();
            CP_WAIT(1);
        } else {
            CP_WAIT(0);
        }
        __syncthreads();   // all threads' copies for buf complete
#pragma unroll
        for (int j = 0; j < 8; j++) {
            float xv  = sX[buf][j][p];
            float dtv = sBC[buf][j][32], dAv = sBC[buf][j][33];
            float coef = dtv * xv;
            float y = 0.f;
#pragma unroll
            for (int n = 0; n < 16; n++) {
                hs[n] = fmaf(hs[n], dAv, coef * sBC[buf][j][n]);
                y = fmaf(hs[n], sBC[buf][j][16 + n], y);
            }
            P *= dAv;
            int s = s0 + gg * 8 + j;
            g_y[rowof(s) * (long)DI + h * HD + p] = fmaf(dp, xv, y);
            if (p == 0) g_P[(size_t)sid * LL + s] = P;
        }
        __syncthreads();   // buf free for overwrite next iteration
    }

    float* Sp = g_S + (size_t)blk * (HD * 16) + p * 16;
#pragma unroll
    for (int n = 0; n < 16; n++) Sp[n] = hs[n];
}

// ---------------- scan pass 2: serial chunk-state propagation ----------------
__global__ __launch_bounds__(64)
void state_scan_k()
{
    int sid = blockIdx.x;
    int p = threadIdx.x;
    float hs[16];
#pragma unroll
    for (int n = 0; n < 16; n++) hs[n] = 0.f;

    for (int c = 0; c < NC; c++) {
        size_t off = ((size_t)(sid * NC + c)) * (HD * 16) + p * 16;
#pragma unroll
        for (int n = 0; n < 16; n++) g_hin[off + n] = hs[n];
        float Pt = g_P[(size_t)sid * LL + c * CL + CL - 1];
#pragma unroll
        for (int n = 0; n < 16; n++) hs[n] = fmaf(hs[n], Pt, g_S[off + n]);
    }
}

// ---------------- scan pass 3: y[s] += P[s] * (C[s] . h_in) ----------------
__global__ __launch_bounds__(64)
void fixup_k()
{
    int blk = blockIdx.x;
    int cm  = blk % (NC - 1);
    int sid = blk / (NC - 1);
    int c   = cm + 1;
    int d = sid >> 7, b = (sid >> 4) & 7, h = sid & 15;
    int p = threadIdx.x;
    long base0 = (long)d * MT + (long)b * LL;

    size_t off = ((size_t)(sid * NC + c)) * (HD * 16) + p * 16;
    float hin[16];
#pragma unroll
    for (int n = 0; n < 16; n++) hin[n] = g_hin[off + n];

    __shared__ float sC[4][16];
    __shared__ float sP[4];
    int s0 = c * CL;

    for (int i = 0; i < CL; i += 4) {
        {
            int tsub = p >> 4, n = p & 15;
            int s = s0 + i + tsub;
            int t = (d == 0) ? s : (LL - 1 - s);
            sC[tsub][n] = g_xbc[(base0 + t) * (long)CD + DI + 16 + n];
            if (n == 0) sP[tsub] = g_P[(size_t)sid * LL + s];
        }
        __syncthreads();
        float av[4];
#pragma unroll
        for (int j = 0; j < 4; j++) {
            float y = 0.f;
#pragma unroll
            for (int n = 0; n < 16; n++) y = fmaf(hin[n], sC[j][n], y);
            av[j] = y;
        }
#pragma unroll
        for (int j = 0; j < 4; j++) {
            int s = s0 + i + j;
            int t = (d == 0) ? s : (LL - 1 - s);
            long row = base0 + t;
            g_y[row * (long)DI + h * HD + p] += sP[j] * av[j];
        }
        __syncthreads();
    }
}

// ---------------- gated RMSNorm ----------------
__global__ __launch_bounds__(256)
void gnorm_k(const float* __restrict__ nwF, const float* __restrict__ nwB)
{
    long r = blockIdx.x;
    int  d = (int)(r / MT);
    const float* nw = (d == 0) ? nwF : nwB;
    const float* yp = g_y  + r * (long)DI;
    const float* zp = g_zx + r * (long)DIP;

    int i0 = threadIdx.x * 4;
    float v[4];
    float ss = 0.f;
#pragma unroll
    for (int j = 0; j < 4; j++) {
        float val = yp[i0 + j] * siluf(zp[i0 + j]);
        v[j] = val;
        ss = fmaf(val, val, ss);
    }
#pragma unroll
    for (int off = 16; off; off >>= 1) ss += __shfl_xor_sync(~0u, ss, off);
    __shared__ float ws[8];
    if ((threadIdx.x & 31) == 0) ws[threadIdx.x >> 5] = ss;
    __syncthreads();
    float tot = ws[0] + ws[1] + ws[2] + ws[3] + ws[4] + ws[5] + ws[6] + ws[7];
    float scale = rsqrtf(tot * (1.f / 1024.f) + 1e-5f);
#pragma unroll
    for (int j = 0; j < 4; j++)
        g_g[r * (long)DI + i0 + j] = v[j] * scale * nw[i0 + j];
}

// ---------------- launch ----------------
extern "C" void kernel_launch(void* const* d_in, const int* in_sizes, int n_in,
                              void* d_out, int out_size)
{
    const float* x    = (const float*)d_in[0];
    const float* ipwF = (const float*)d_in[1];
    const float* cwF  = (const float*)d_in[2];
    const float* cbF  = (const float*)d_in[3];
    const float* dbF  = (const float*)d_in[4];
    const float* alF  = (const float*)d_in[5];
    const float* dpF  = (const float*)d_in[6];
    const float* nwF  = (const float*)d_in[7];
    const float* opF  = (const float*)d_in[8];
    const float* ipwB = (const float*)d_in[9];
    const float* cwB  = (const float*)d_in[10];
    const float* cbB  = (const float*)d_in[11];
    const float* dbB  = (const float*)d_in[12];
    const float* alB  = (const float*)d_in[13];
    const float* dpB  = (const float*)d_in[14];
    const float* nwB  = (const float*)d_in[15];
    const float* opB  = (const float*)d_in[16];
    float* out = (float*)d_out;

    float *zx_d, *g_d;
    cudaGetSymbolAddress((void**)&zx_d, g_zx);
    cudaGetSymbolAddress((void**)&g_d,  g_g);

    cudaFuncSetAttribute((const void*)gemm_in,
                         cudaFuncAttributeMaxDynamicSharedMemorySize, GEMM_SMEM);
    cudaFuncSetAttribute((const void*)gemm_out,
                         cudaFuncAttributeMaxDynamicSharedMemorySize, GEMM_SMEM);

    // 1) in_proj both directions (grid.z = dir), BN=256 / warp 64x64
    gemm_in<<<dim3(9, 128, 2), 256, GEMM_SMEM>>>(x, ipwF, ipwB, zx_d);

    // 2) depthwise conv + silu
    {
        long total = 2L * 8 * (LL / CTT) * CD;
        conv_silu_k<<<(unsigned)(total / 256), 256>>>(cwF, cbF, cwB, cbB);
    }

    // 3) dt / dA (exact fp32, W in smem)
    dadt_k<<<512, 256>>>(x, ipwF, ipwB, dbF, alF, dbB, alB);

    // 4) chunked selective scan
    chunk_scan_k<<<NSCAN * NC, 64>>>(dpF, dpB);
    state_scan_k<<<NSCAN, 64>>>();
    fixup_k<<<NSCAN * (NC - 1), 64>>>();

    // 5) gated RMSNorm
    gnorm_k<<<2 * MT, 256>>>(nwF, nwB);

    // 6) out_proj: single GEMM, K-concat fwd+bwd, BN=256
    gemm_out<<<dim3(2, 128), 256, GEMM_SMEM>>>(g_d, g_d + (size_t)MT * DI, opF, opB, out);
}

// round 9
// speedup vs baseline: 1.1269x; 1.1269x over previous
#include <cuda_runtime.h>
#include <math.h>
#include <stdint.h>

#define BB 8
#define LL 2048
#define DM 512
#define DI 1024
#define NH 16
#define HD 64
#define CD 1056
#define DIP 2096
#define MT (BB*LL)      // 16384 tokens
#define CL 128          // scan chunk length
#define NC (LL/CL)      // 16 chunks
#define NSCAN 256       // 2 dirs * 8 batch * 16 heads

// ---------------- scratch (static device globals; no allocation) ----------------
__device__ float g_zx [2ull*MT*DIP];
__device__ float g_xbc[2ull*MT*CD];
__device__ float g_dt [2ull*MT*NH];
__device__ float g_dA [2ull*MT*NH];
__device__ float g_y  [2ull*MT*DI];
__device__ float g_g  [2ull*MT*DI];
__device__ float g_P  [(size_t)NSCAN*LL];
__device__ float g_S  [(size_t)NSCAN*NC*HD*16];
__device__ float g_hin[(size_t)NSCAN*NC*HD*16];

__device__ __forceinline__ float siluf(float v)     { return v / (1.f + expf(-v)); }
__device__ __forceinline__ float softplusf(float v) { return fmaxf(v, 0.f) + log1pf(expf(-fabsf(v))); }
__device__ __forceinline__ uint32_t f2tf32(float f) {
    uint32_t r; asm("cvt.rna.tf32.f32 %0, %1;" : "=r"(r) : "f"(f)); return r;
}
__device__ __forceinline__ void mma8(float* c, const uint32_t* a, const uint32_t* b) {
    asm volatile(
        "mma.sync.aligned.m16n8k8.row.col.f32.tf32.tf32.f32 "
        "{%0,%1,%2,%3}, {%4,%5,%6,%7}, {%8,%9}, {%0,%1,%2,%3};"
        : "+f"(c[0]), "+f"(c[1]), "+f"(c[2]), "+f"(c[3])
        : "r"(a[0]), "r"(a[1]), "r"(a[2]), "r"(a[3]), "r"(b[0]), "r"(b[1]));
}
__device__ __forceinline__ void cpa16(const void* sp, const void* g) {
    uint32_t s = (uint32_t)__cvta_generic_to_shared(sp);
    asm volatile("cp.async.cg.shared.global [%0], [%1], 16;" :: "r"(s), "l"(g));
}
__device__ __forceinline__ void cpa16p(const void* sp, const void* g, bool pred) {
    uint32_t s = (uint32_t)__cvta_generic_to_shared(sp);
    int sz = pred ? 16 : 0;
    asm volatile("cp.async.cg.shared.global [%0], [%1], 16, %2;" :: "r"(s), "l"(g), "r"(sz));
}
__device__ __forceinline__ void cpa4(const void* sp, const void* g) {
    uint32_t s = (uint32_t)__cvta_generic_to_shared(sp);
    asm volatile("cp.async.ca.shared.global [%0], [%1], 4;" :: "r"(s), "l"(g));
}
#define CP_COMMIT() asm volatile("cp.async.commit_group;" ::: "memory")
#define CP_WAIT(n)  asm volatile("cp.async.wait_group %0;" :: "n"(n) : "memory")

// ============================================================================
// GEMM (BM=128, BN=128, BK=32; 8 warps 2x4, warp tile 64x32), cp.async 2-stage.
// smem [row][36] floats per stage: conflict-free fragment reads.
// Dynamic smem: 2 stages x (A 128x36 + B 128x36) x 4B = 73728 B. 2 CTA/SM.
// ============================================================================
#define GEMM_SMEM 73728
#define ASM(st,r,k) sA[((st)*128 + (r))*36 + (k)]
#define BSM(st,r,k) sB[((st)*128 + (r))*36 + (k)]

#define GEMM_PROLOGUE \
    extern __shared__ float smp[]; \
    float* sA = smp; \
    float* sB = smp + 2*128*36; \
    const int tid  = threadIdx.x; \
    const int lane = tid & 31; \
    const int wid  = tid >> 5; \
    const int mw   = wid & 1; \
    const int nw   = wid >> 1; \
    const int g = lane >> 2; \
    const int q = lane & 3; \
    float acc[4][4][4]; \
    _Pragma("unroll") for (int i = 0; i < 4; i++) \
    _Pragma("unroll") for (int j = 0; j < 4; j++) \
    _Pragma("unroll") for (int r = 0; r < 4; r++) acc[i][j][r] = 0.f;

#define GEMM_COMPUTE(cur) \
    _Pragma("unroll") \
    for (int kk = 0; kk < 32; kk += 8) { \
        uint32_t af[4][4], bf[4][2]; \
        _Pragma("unroll") \
        for (int mt = 0; mt < 4; mt++) { \
            int row = mw * 64 + mt * 16 + g; \
            af[mt][0] = f2tf32(ASM(cur, row    , kk + q    )); \
            af[mt][1] = f2tf32(ASM(cur, row + 8, kk + q    )); \
            af[mt][2] = f2tf32(ASM(cur, row    , kk + q + 4)); \
            af[mt][3] = f2tf32(ASM(cur, row + 8, kk + q + 4)); \
        } \
        _Pragma("unroll") \
        for (int nt = 0; nt < 4; nt++) { \
            int col = nw * 32 + nt * 8 + g; \
            bf[nt][0] = f2tf32(BSM(cur, col, kk + q    )); \
            bf[nt][1] = f2tf32(BSM(cur, col, kk + q + 4)); \
        } \
        _Pragma("unroll") \
        for (int mt = 0; mt < 4; mt++) \
        _Pragma("unroll") \
        for (int nt = 0; nt < 4; nt++) \
            mma8(acc[mt][nt], af[mt], bf[nt]); \
    }

#define GEMM_MAINLOOP(T) \
    load_tile(0, 0); CP_COMMIT(); \
    load_tile(1, 1); CP_COMMIT(); \
    for (int kt = 0; kt < (T); kt++) { \
        const int cur = kt & 1; \
        if (kt + 1 < (T)) { CP_WAIT(1); } else { CP_WAIT(0); } \
        __syncthreads(); \
        GEMM_COMPUTE(cur) \
        __syncthreads(); \
        if (kt + 2 < (T)) { load_tile(kt + 2, cur); CP_COMMIT(); } \
    }

// ---------------- in_proj: grid (17,128,2); z selects direction ----------------
__global__ void __launch_bounds__(256, 2)
gemm_in(const float* __restrict__ A, const float* __restrict__ B0,
        const float* __restrict__ B1, float* __restrict__ Cb)
{
    const float* B = blockIdx.z ? B1 : B0;
    float* C = Cb + (size_t)blockIdx.z * MT * DIP;
    const int m0 = blockIdx.y * 128, n0 = blockIdx.x * 128;
    const int N = DIP, K = DM;

    GEMM_PROLOGUE

    auto load_tile = [&](int kt, int buf) {
        const int k0 = kt << 5;
#pragma unroll
        for (int i = 0; i < 4; i++) {
            int id  = tid + (i << 8);
            int row = id >> 3;
            int ce  = (id & 7) << 2;
            cpa16(&ASM(buf, row, ce), A + (size_t)(m0 + row) * K + k0 + ce);
            cpa16p(&BSM(buf, row, ce), B + (size_t)(n0 + row) * K + k0 + ce,
                   (n0 + row) < N);
        }
    };

    GEMM_MAINLOOP(K >> 5)

#pragma unroll
    for (int mt = 0; mt < 4; mt++) {
        int row = m0 + mw * 64 + mt * 16 + g;
#pragma unroll
        for (int nt = 0; nt < 4; nt++) {
            int n = n0 + nw * 32 + nt * 8 + q * 2;
            if (n < N) {
                *(float2*)(C + (size_t)row * DIP + n) =
                    make_float2(acc[mt][nt][0], acc[mt][nt][1]);
                *(float2*)(C + (size_t)(row + 8) * DIP + n) =
                    make_float2(acc[mt][nt][2], acc[mt][nt][3]);
            }
        }
    }
}

// ---------------- out_proj: K-concat of fwd+bwd (K=2048) -> single write ----------------
__global__ void __launch_bounds__(256, 2)
gemm_out(const float* __restrict__ A0, const float* __restrict__ A1,
         const float* __restrict__ B0, const float* __restrict__ B1,
         float* __restrict__ C)
{
    const int m0 = blockIdx.y * 128, n0 = blockIdx.x * 128;
    const int K = 2 * DI;

    GEMM_PROLOGUE

    auto load_tile = [&](int kt, int buf) {
        const int k0 = kt << 5;
        const float* Ap; const float* Bp; int kl;
        if (k0 < DI) { Ap = A0; Bp = B0; kl = k0; }
        else         { Ap = A1; Bp = B1; kl = k0 - DI; }
#pragma unroll
        for (int i = 0; i < 4; i++) {
            int id  = tid + (i << 8);
            int row = id >> 3;
            int ce  = (id & 7) << 2;
            cpa16(&ASM(buf, row, ce), Ap + (size_t)(m0 + row) * DI + kl + ce);
            cpa16(&BSM(buf, row, ce), Bp + (size_t)(n0 + row) * DI + kl + ce);
        }
    };

    GEMM_MAINLOOP(K >> 5)

#pragma unroll
    for (int mt = 0; mt < 4; mt++) {
        int row = m0 + mw * 64 + mt * 16 + g;
#pragma unroll
        for (int nt = 0; nt < 4; nt++) {
            int n = n0 + nw * 32 + nt * 8 + q * 2;
            *(float2*)(C + (size_t)row * DM + n) =
                make_float2(acc[mt][nt][0], acc[mt][nt][1]);
            *(float2*)(C + (size_t)(row + 8) * DM + n) =
                make_float2(acc[mt][nt][2], acc[mt][nt][3]);
        }
    }
}

// ---------------- depthwise conv(4) + bias + SiLU, 8 outputs per thread ----------------
#define CTT 8
__global__ __launch_bounds__(256)
void conv_silu_k(const float* __restrict__ cwF, const float* __restrict__ cbF,
                 const float* __restrict__ cwB, const float* __restrict__ cbB)
{
    long idx = (long)blockIdx.x * 256 + threadIdx.x;
    int  c  = (int)(idx % CD);
    long q2 = idx / CD;
    int  tg = (int)(q2 & (LL / CTT - 1));
    int  bd = (int)(q2 >> 8);
    int  b  = bd & 7, d = bd >> 3;
    int  t0 = tg * CTT;

    const float* wv = (d == 0 ? cwF : cwB) + c * 4;
    float w0 = wv[0], w1 = wv[1], w2 = wv[2], w3 = wv[3];
    float bias = (d == 0 ? cbF : cbB)[c];
    long rbase = (long)d * MT + (long)b * LL;
    const float* zin = g_zx + rbase * (long)DIP + DI + c;
    float* outp = g_xbc + (rbase + t0) * (long)CD + c;

    float in[CTT + 3];
    if (d == 0) {
#pragma unroll
        for (int j = 0; j < CTT + 3; j++) {
            int tt = t0 - 3 + j;
            in[j] = (tt >= 0) ? zin[(long)tt * DIP] : 0.f;
        }
#pragma unroll
        for (int i = 0; i < CTT; i++) {
            float a = bias;
            a = fmaf(w0, in[i], a); a = fmaf(w1, in[i+1], a);
            a = fmaf(w2, in[i+2], a); a = fmaf(w3, in[i+3], a);
            outp[(long)i * CD] = siluf(a);
        }
    } else {
#pragma unroll
        for (int j = 0; j < CTT + 3; j++) {
            int tt = t0 + j;
            in[j] = (tt < LL) ? zin[(long)tt * DIP] : 0.f;
        }
#pragma unroll
        for (int i = 0; i < CTT; i++) {
            float a = bias;
            a = fmaf(w3, in[i], a); a = fmaf(w2, in[i+1], a);
            a = fmaf(w1, in[i+2], a); a = fmaf(w0, in[i+3], a);
            outp[(long)i * CD] = siluf(a);
        }
    }
}

// ---------------- dt exact fp32, W cached in smem; 64 tokens per block ----------------
__global__ __launch_bounds__(256)
void dadt_k(const float* __restrict__ x,
            const float* __restrict__ ipwF, const float* __restrict__ ipwB,
            const float* __restrict__ dbF,  const float* __restrict__ alF,
            const float* __restrict__ dbB,  const float* __restrict__ alB)
{
    __shared__ float sW[16][512];
    int blk = blockIdx.x;
    int d   = blk >> 8;
    int tb  = blk & 255;
    int tid = threadIdx.x;

    const float* W = (d ? ipwB : ipwF) + (size_t)(DI + CD) * DM;
#pragma unroll
    for (int j = 0; j < 8; j++)
        ((float4*)&sW[0][0])[j * 256 + tid] = ((const float4*)W)[j * 256 + tid];
    __syncthreads();

    int h = tid >> 4, l = tid & 15;
    float db = (d ? dbB : dbF)[h];
    float A  = -expf((d ? alB : alF)[h]);

    for (int tk = 0; tk < 64; tk++) {
        int token = tb * 64 + tk;
        const float4* xr = (const float4*)(x + (size_t)token * DM);
        const float4* wr = (const float4*)&sW[h][0];
        float s = 0.f;
#pragma unroll
        for (int j = 0; j < 8; j++) {
            float4 xv = xr[l + 16 * j];
            float4 wv = wr[l + 16 * j];
            s = fmaf(xv.x, wv.x, s); s = fmaf(xv.y, wv.y, s);
            s = fmaf(xv.z, wv.z, s); s = fmaf(xv.w, wv.w, s);
        }
        s += __shfl_xor_sync(~0u, s, 1);
        s += __shfl_xor_sync(~0u, s, 2);
        s += __shfl_xor_sync(~0u, s, 4);
        s += __shfl_xor_sync(~0u, s, 8);
        if (l == 0) {
            float dt = softplusf(s + db);
            size_t r = (size_t)d * MT + token;
            g_dt[r * NH + h] = dt;
            g_dA[r * NH + h] = expf(dt * A);
        }
    }
}

// ---------------- scan pass 1: chunk scans, cp.async smem double-buffer ----------------
__global__ __launch_bounds__(64)
void chunk_scan_k(const float* __restrict__ DpF, const float* __restrict__ DpB)
{
    int blk = blockIdx.x;
    int c   = blk & (NC - 1);
    int sid = blk >> 4;
    int d = sid >> 7, b = (sid >> 4) & 7, h = sid & 15;
    int p = threadIdx.x;

    __shared__ float sBC[2][8][36];   // [buf][j][B16,C16,dt,dA,pad]
    __shared__ float sX [2][8][64];   // [buf][j][p]
    float hs[16];
#pragma unroll
    for (int n = 0; n < 16; n++) hs[n] = 0.f;
    float dp = (d == 0 ? DpF : DpB)[h];
    long base0 = (long)d * MT + (long)b * LL;
    int s0 = c * CL;

    auto rowof = [&](int s) -> long {
        int t = (d == 0) ? s : (LL - 1 - s);
        return base0 + t;
    };
    auto loadgrp = [&](int gg, int buf) {
        {
            int j = p >> 3, seg = p & 7;
            long row = rowof(s0 + gg * 8 + j);
            cpa16(&sBC[buf][j][seg * 4], &g_xbc[row * (long)CD + DI + seg * 4]);
        }
#pragma unroll
        for (int it = 0; it < 2; it++) {
            int idx = p + it * 64;
            int j = idx >> 4, c4 = (idx & 15) << 2;
            long row = rowof(s0 + gg * 8 + j);
            cpa16(&sX[buf][j][c4], &g_xbc[row * (long)CD + h * HD + c4]);
        }
        if (p < 8) {
            long row = rowof(s0 + gg * 8 + p);
            cpa4(&sBC[buf][p][32], &g_dt[row * (long)NH + h]);
        } else if (p < 16) {
            long row = rowof(s0 + gg * 8 + (p - 8));
            cpa4(&sBC[buf][p - 8][33], &g_dA[row * (long)NH + h]);
        }
    };

    loadgrp(0, 0);
    CP_COMMIT();

    float P = 1.f;
    for (int gg = 0; gg < 16; gg++) {
        int buf = gg & 1;
        if (gg + 1 < 16) {
            loadgrp(gg + 1, buf ^ 1);
            CP_COMMIT();
            CP_WAIT(1);
        } else {
            CP_WAIT(0);
        }
        __syncthreads();
#pragma unroll
        for (int j = 0; j < 8; j++) {
            float xv  = sX[buf][j][p];
            float dtv = sBC[buf][j][32], dAv = sBC[buf][j][33];
            float coef = dtv * xv;
            float y = 0.f;
#pragma unroll
            for (int n = 0; n < 16; n++) {
                hs[n] = fmaf(hs[n], dAv, coef * sBC[buf][j][n]);
                y = fmaf(hs[n], sBC[buf][j][16 + n], y);
            }
            P *= dAv;
            int s = s0 + gg * 8 + j;
            g_y[rowof(s) * (long)DI + h * HD + p] = fmaf(dp, xv, y);
            if (p == 0) g_P[(size_t)sid * LL + s] = P;
        }
        __syncthreads();
    }

    float* Sp = g_S + (size_t)blk * (HD * 16) + p * 16;
#pragma unroll
    for (int n = 0; n < 16; n++) Sp[n] = hs[n];
}

// ---------------- scan pass 2: serial chunk-state propagation ----------------
__global__ __launch_bounds__(64)
void state_scan_k()
{
    int sid = blockIdx.x;
    int p = threadIdx.x;
    float hs[16];
#pragma unroll
    for (int n = 0; n < 16; n++) hs[n] = 0.f;

    for (int c = 0; c < NC; c++) {
        size_t off = ((size_t)(sid * NC + c)) * (HD * 16) + p * 16;
#pragma unroll
        for (int n = 0; n < 16; n++) g_hin[off + n] = hs[n];
        float Pt = g_P[(size_t)sid * LL + c * CL + CL - 1];
#pragma unroll
        for (int n = 0; n < 16; n++) hs[n] = fmaf(hs[n], Pt, g_S[off + n]);
    }
}

// ---------------- scan pass 3: y[s] += P[s] * (C[s] . h_in) ----------------
__global__ __launch_bounds__(64)
void fixup_k()
{
    int blk = blockIdx.x;
    int cm  = blk % (NC - 1);
    int sid = blk / (NC - 1);
    int c   = cm + 1;
    int d = sid >> 7, b = (sid >> 4) & 7, h = sid & 15;
    int p = threadIdx.x;
    long base0 = (long)d * MT + (long)b * LL;

    size_t off = ((size_t)(sid * NC + c)) * (HD * 16) + p * 16;
    float hin[16];
#pragma unroll
    for (int n = 0; n < 16; n++) hin[n] = g_hin[off + n];

    __shared__ float sC[4][16];
    __shared__ float sP[4];
    int s0 = c * CL;

    for (int i = 0; i < CL; i += 4) {
        {
            int tsub = p >> 4, n = p & 15;
            int s = s0 + i + tsub;
            int t = (d == 0) ? s : (LL - 1 - s);
            sC[tsub][n] = g_xbc[(base0 + t) * (long)CD + DI + 16 + n];
            if (n == 0) sP[tsub] = g_P[(size_t)sid * LL + s];
        }
        __syncthreads();
        float av[4];
#pragma unroll
        for (int j = 0; j < 4; j++) {
            float y = 0.f;
#pragma unroll
            for (int n = 0; n < 16; n++) y = fmaf(hin[n], sC[j][n], y);
            av[j] = y;
        }
#pragma unroll
        for (int j = 0; j < 4; j++) {
            int s = s0 + i + j;
            int t = (d == 0) ? s : (LL - 1 - s);
            long row = base0 + t;
            g_y[row * (long)DI + h * HD + p] += sP[j] * av[j];
        }
        __syncthreads();
    }
}

// ---------------- gated RMSNorm ----------------
__global__ __launch_bounds__(256)
void gnorm_k(const float* __restrict__ nwF, const float* __restrict__ nwB)
{
    long r = blockIdx.x;
    int  d = (int)(r / MT);
    const float* nw = (d == 0) ? nwF : nwB;
    const float* yp = g_y  + r * (long)DI;
    const float* zp = g_zx + r * (long)DIP;

    int i0 = threadIdx.x * 4;
    float v[4];
    float ss = 0.f;
#pragma unroll
    for (int j = 0; j < 4; j++) {
        float val = yp[i0 + j] * siluf(zp[i0 + j]);
        v[j] = val;
        ss = fmaf(val, val, ss);
    }
#pragma unroll
    for (int off = 16; off; off >>= 1) ss += __shfl_xor_sync(~0u, ss, off);
    __shared__ float ws[8];
    if ((threadIdx.x & 31) == 0) ws[threadIdx.x >> 5] = ss;
    __syncthreads();
    float tot = ws[0] + ws[1] + ws[2] + ws[3] + ws[4] + ws[5] + ws[6] + ws[7];
    float scale = rsqrtf(tot * (1.f / 1024.f) + 1e-5f);
#pragma unroll
    for (int j = 0; j < 4; j++)
        g_g[r * (long)DI + i0 + j] = v[j] * scale * nw[i0 + j];
}

// ---------------- launch ----------------
extern "C" void kernel_launch(void* const* d_in, const int* in_sizes, int n_in,
                              void* d_out, int out_size)
{
    const float* x    = (const float*)d_in[0];
    const float* ipwF = (const float*)d_in[1];
    const float* cwF  = (const float*)d_in[2];
    const float* cbF  = (const float*)d_in[3];
    const float* dbF  = (const float*)d_in[4];
    const float* alF  = (const float*)d_in[5];
    const float* dpF  = (const float*)d_in[6];
    const float* nwF  = (const float*)d_in[7];
    const float* opF  = (const float*)d_in[8];
    const float* ipwB = (const float*)d_in[9];
    const float* cwB  = (const float*)d_in[10];
    const float* cbB  = (const float*)d_in[11];
    const float* dbB  = (const float*)d_in[12];
    const float* alB  = (const float*)d_in[13];
    const float* dpB  = (const float*)d_in[14];
    const float* nwB  = (const float*)d_in[15];
    const float* opB  = (const float*)d_in[16];
    float* out = (float*)d_out;

    float *zx_d, *g_d;
    cudaGetSymbolAddress((void**)&zx_d, g_zx);
    cudaGetSymbolAddress((void**)&g_d,  g_g);

    cudaFuncSetAttribute((const void*)gemm_in,
                         cudaFuncAttributeMaxDynamicSharedMemorySize, GEMM_SMEM);
    cudaFuncSetAttribute((const void*)gemm_out,
                         cudaFuncAttributeMaxDynamicSharedMemorySize, GEMM_SMEM);

    // 1) in_proj both directions (grid.z = dir), BK=32 cp.async tf32 MMA
    gemm_in<<<dim3(17, 128, 2), 256, GEMM_SMEM>>>(x, ipwF, ipwB, zx_d);

    // 2) depthwise conv + silu
    {
        long total = 2L * 8 * (LL / CTT) * CD;
        conv_silu_k<<<(unsigned)(total / 256), 256>>>(cwF, cbF, cwB, cbB);
    }

    // 3) dt / dA (exact fp32, W in smem)
    dadt_k<<<512, 256>>>(x, ipwF, ipwB, dbF, alF, dbB, alB);

    // 4) chunked selective scan (cp.async staged)
    chunk_scan_k<<<NSCAN * NC, 64>>>(dpF, dpB);
    state_scan_k<<<NSCAN, 64>>>();
    fixup_k<<<NSCAN * (NC - 1), 64>>>();

    // 5) gated RMSNorm
    gnorm_k<<<2 * MT, 256>>>(nwF, nwB);

    // 6) out_proj: single GEMM, K-concat fwd+bwd
    gemm_out<<<dim3(4, 128), 256, GEMM_SMEM>>>(g_d, g_d + (size_t)MT * DI, opF, opB, out);
}

// round 10
// speedup vs baseline: 1.1373x; 1.0093x over previous
#include <cuda_runtime.h>
#include <math.h>
#include <stdint.h>

#define BB 8
#define LL 2048
#define DM 512
#define DI 1024
#define NH 16
#define HD 64
#define CD 1056
#define DIP 2096
#define MT (BB*LL)      // 16384 tokens
#define CL 128          // scan chunk length
#define NC (LL/CL)      // 16 chunks
#define NSCAN 256       // 2 dirs * 8 batch * 16 heads

// ---------------- scratch (static device globals; no allocation) ----------------
__device__ float g_zx [2ull*MT*DIP];
__device__ float g_xbc[2ull*MT*CD];
__device__ float g_dt [2ull*MT*NH];
__device__ float g_dA [2ull*MT*NH];
__device__ float g_y  [2ull*MT*DI];
__device__ float g_g  [2ull*MT*DI];
__device__ float g_P  [(size_t)NSCAN*LL];
__device__ float g_S  [(size_t)NSCAN*NC*HD*16];
__device__ float g_hin[(size_t)NSCAN*NC*HD*16];

__device__ __forceinline__ float siluf(float v)     { return v / (1.f + expf(-v)); }
__device__ __forceinline__ float softplusf(float v) { return fmaxf(v, 0.f) + log1pf(expf(-fabsf(v))); }
__device__ __forceinline__ uint32_t f2tf32(float f) {
    uint32_t r; asm("cvt.rna.tf32.f32 %0, %1;" : "=r"(r) : "f"(f)); return r;
}
__device__ __forceinline__ void mma8(float* c, const uint32_t* a, const uint32_t* b) {
    asm volatile(
        "mma.sync.aligned.m16n8k8.row.col.f32.tf32.tf32.f32 "
        "{%0,%1,%2,%3}, {%4,%5,%6,%7}, {%8,%9}, {%0,%1,%2,%3};"
        : "+f"(c[0]), "+f"(c[1]), "+f"(c[2]), "+f"(c[3])
        : "r"(a[0]), "r"(a[1]), "r"(a[2]), "r"(a[3]), "r"(b[0]), "r"(b[1]));
}
__device__ __forceinline__ void cpa16(const void* sp, const void* g) {
    uint32_t s = (uint32_t)__cvta_generic_to_shared(sp);
    asm volatile("cp.async.cg.shared.global [%0], [%1], 16;" :: "r"(s), "l"(g));
}
__device__ __forceinline__ void cpa16p(const void* sp, const void* g, bool pred) {
    uint32_t s = (uint32_t)__cvta_generic_to_shared(sp);
    int sz = pred ? 16 : 0;
    asm volatile("cp.async.cg.shared.global [%0], [%1], 16, %2;" :: "r"(s), "l"(g), "r"(sz));
}
__device__ __forceinline__ void cpa4(const void* sp, const void* g) {
    uint32_t s = (uint32_t)__cvta_generic_to_shared(sp);
    asm volatile("cp.async.ca.shared.global [%0], [%1], 4;" :: "r"(s), "l"(g));
}
#define CP_COMMIT() asm volatile("cp.async.commit_group;" ::: "memory")
#define CP_WAIT(n)  asm volatile("cp.async.wait_group %0;" :: "n"(n) : "memory")

// ============================================================================
// GEMM (BM=128, BN=128, BK=32; 8 warps 2x4, warp tile 64x32), cp.async 3-stage.
// smem [row][36] floats per stage: conflict-free fragment reads.
// Dynamic smem: 3 stages x (A 128x36 + B 128x36) x 4B = 110592 B. 2 CTA/SM.
// ============================================================================
#define GEMM_SMEM 110592
#define ASM(st,r,k) sA[((st)*128 + (r))*36 + (k)]
#define BSM(st,r,k) sB[((st)*128 + (r))*36 + (k)]

#define GEMM_PROLOGUE \
    extern __shared__ float smp[]; \
    float* sA = smp; \
    float* sB = smp + 3*128*36; \
    const int tid  = threadIdx.x; \
    const int lane = tid & 31; \
    const int wid  = tid >> 5; \
    const int mw   = wid & 1; \
    const int nw   = wid >> 1; \
    const int g = lane >> 2; \
    const int q = lane & 3; \
    float acc[4][4][4]; \
    _Pragma("unroll") for (int i = 0; i < 4; i++) \
    _Pragma("unroll") for (int j = 0; j < 4; j++) \
    _Pragma("unroll") for (int r = 0; r < 4; r++) acc[i][j][r] = 0.f;

#define GEMM_COMPUTE(cur) \
    _Pragma("unroll") \
    for (int kk = 0; kk < 32; kk += 8) { \
        uint32_t af[4][4], bf[4][2]; \
        _Pragma("unroll") \
        for (int mt = 0; mt < 4; mt++) { \
            int row = mw * 64 + mt * 16 + g; \
            af[mt][0] = f2tf32(ASM(cur, row    , kk + q    )); \
            af[mt][1] = f2tf32(ASM(cur, row + 8, kk + q    )); \
            af[mt][2] = f2tf32(ASM(cur, row    , kk + q + 4)); \
            af[mt][3] = f2tf32(ASM(cur, row + 8, kk + q + 4)); \
        } \
        _Pragma("unroll") \
        for (int nt = 0; nt < 4; nt++) { \
            int col = nw * 32 + nt * 8 + g; \
            bf[nt][0] = f2tf32(BSM(cur, col, kk + q    )); \
            bf[nt][1] = f2tf32(BSM(cur, col, kk + q + 4)); \
        } \
        _Pragma("unroll") \
        for (int mt = 0; mt < 4; mt++) \
        _Pragma("unroll") \
        for (int nt = 0; nt < 4; nt++) \
            mma8(acc[mt][nt], af[mt], bf[nt]); \
    }

#define GEMM_MAINLOOP(T) \
    load_tile(0, 0); CP_COMMIT(); \
    load_tile(1, 1); CP_COMMIT(); \
    load_tile(2, 2); CP_COMMIT(); \
    for (int kt = 0; kt < (T); kt++) { \
        const int cur = kt % 3; \
        if (kt + 2 < (T)) { CP_WAIT(2); } \
        else if (kt + 1 < (T)) { CP_WAIT(1); } \
        else { CP_WAIT(0); } \
        __syncthreads(); \
        GEMM_COMPUTE(cur) \
        __syncthreads(); \
        if (kt + 3 < (T)) { load_tile(kt + 3, cur); CP_COMMIT(); } \
    }

// ---------------- in_proj (+ fused dadt tail blocks): grid (18,128,2) ----------------
__global__ void __launch_bounds__(256, 2)
gemm_in(const float* __restrict__ A, const float* __restrict__ B0,
        const float* __restrict__ B1, float* __restrict__ Cb,
        const float* __restrict__ dbF, const float* __restrict__ alF,
        const float* __restrict__ dbB, const float* __restrict__ alB)
{
    if (blockIdx.x == 17) {
        // ---- dadt branch: exact-fp32 dt/dA for 128 tokens, dir = blockIdx.z ----
        extern __shared__ float smp[];
        float (*sW)[512] = (float(*)[512])smp;
        const int d  = blockIdx.z;
        const int tb = blockIdx.y;          // 128 tokens per block
        const int tid = threadIdx.x;
        const float* W = (d ? B1 : B0) + (size_t)(DI + CD) * DM;
#pragma unroll
        for (int j = 0; j < 8; j++)
            ((float4*)&sW[0][0])[j * 256 + tid] = ((const float4*)W)[j * 256 + tid];
        __syncthreads();

        const int h = tid >> 4, l = tid & 15;
        const float db = (d ? dbB : dbF)[h];
        const float Av = -expf((d ? alB : alF)[h]);

        for (int tk = 0; tk < 128; tk++) {
            int token = tb * 128 + tk;
            const float4* xr = (const float4*)(A + (size_t)token * DM);
            const float4* wr = (const float4*)&sW[h][0];
            float s = 0.f;
#pragma unroll
            for (int j = 0; j < 8; j++) {
                float4 xv = xr[l + 16 * j];
                float4 wv = wr[l + 16 * j];
                s = fmaf(xv.x, wv.x, s); s = fmaf(xv.y, wv.y, s);
                s = fmaf(xv.z, wv.z, s); s = fmaf(xv.w, wv.w, s);
            }
            s += __shfl_xor_sync(~0u, s, 1);
            s += __shfl_xor_sync(~0u, s, 2);
            s += __shfl_xor_sync(~0u, s, 4);
            s += __shfl_xor_sync(~0u, s, 8);
            if (l == 0) {
                float dt = softplusf(s + db);
                size_t r = (size_t)d * MT + token;
                g_dt[r * NH + h] = dt;
                g_dA[r * NH + h] = expf(dt * Av);
            }
        }
        return;
    }

    const float* B = blockIdx.z ? B1 : B0;
    float* C = Cb + (size_t)blockIdx.z * MT * DIP;
    const int m0 = blockIdx.y * 128, n0 = blockIdx.x * 128;
    const int N = DIP, K = DM;

    GEMM_PROLOGUE

    auto load_tile = [&](int kt, int buf) {
        const int k0 = kt << 5;
#pragma unroll
        for (int i = 0; i < 4; i++) {
            int id  = tid + (i << 8);
            int row = id >> 3;
            int ce  = (id & 7) << 2;
            cpa16(&ASM(buf, row, ce), A + (size_t)(m0 + row) * K + k0 + ce);
            cpa16p(&BSM(buf, row, ce), B + (size_t)(n0 + row) * K + k0 + ce,
                   (n0 + row) < N);
        }
    };

    GEMM_MAINLOOP(K >> 5)

#pragma unroll
    for (int mt = 0; mt < 4; mt++) {
        int row = m0 + mw * 64 + mt * 16 + g;
#pragma unroll
        for (int nt = 0; nt < 4; nt++) {
            int n = n0 + nw * 32 + nt * 8 + q * 2;
            if (n < N) {
                *(float2*)(C + (size_t)row * DIP + n) =
                    make_float2(acc[mt][nt][0], acc[mt][nt][1]);
                *(float2*)(C + (size_t)(row + 8) * DIP + n) =
                    make_float2(acc[mt][nt][2], acc[mt][nt][3]);
            }
        }
    }
}

// ---------------- out_proj: K-concat of fwd+bwd (K=2048) -> single write ----------------
__global__ void __launch_bounds__(256, 2)
gemm_out(const float* __restrict__ A0, const float* __restrict__ A1,
         const float* __restrict__ B0, const float* __restrict__ B1,
         float* __restrict__ C)
{
    const int m0 = blockIdx.y * 128, n0 = blockIdx.x * 128;
    const int K = 2 * DI;

    GEMM_PROLOGUE

    auto load_tile = [&](int kt, int buf) {
        const int k0 = kt << 5;
        const float* Ap; const float* Bp; int kl;
        if (k0 < DI) { Ap = A0; Bp = B0; kl = k0; }
        else         { Ap = A1; Bp = B1; kl = k0 - DI; }
#pragma unroll
        for (int i = 0; i < 4; i++) {
            int id  = tid + (i << 8);
            int row = id >> 3;
            int ce  = (id & 7) << 2;
            cpa16(&ASM(buf, row, ce), Ap + (size_t)(m0 + row) * DI + kl + ce);
            cpa16(&BSM(buf, row, ce), Bp + (size_t)(n0 + row) * DI + kl + ce);
        }
    };

    GEMM_MAINLOOP(K >> 5)

#pragma unroll
    for (int mt = 0; mt < 4; mt++) {
        int row = m0 + mw * 64 + mt * 16 + g;
#pragma unroll
        for (int nt = 0; nt < 4; nt++) {
            int n = n0 + nw * 32 + nt * 8 + q * 2;
            *(float2*)(C + (size_t)row * DM + n) =
                make_float2(acc[mt][nt][0], acc[mt][nt][1]);
            *(float2*)(C + (size_t)(row + 8) * DM + n) =
                make_float2(acc[mt][nt][2], acc[mt][nt][3]);
        }
    }
}

// ---------------- depthwise conv(4) + bias + SiLU, 8 outputs per thread ----------------
#define CTT 8
__global__ __launch_bounds__(256)
void conv_silu_k(const float* __restrict__ cwF, const float* __restrict__ cbF,
                 const float* __restrict__ cwB, const float* __restrict__ cbB)
{
    long idx = (long)blockIdx.x * 256 + threadIdx.x;
    int  c  = (int)(idx % CD);
    long q2 = idx / CD;
    int  tg = (int)(q2 & (LL / CTT - 1));
    int  bd = (int)(q2 >> 8);
    int  b  = bd & 7, d = bd >> 3;
    int  t0 = tg * CTT;

    const float* wv = (d == 0 ? cwF : cwB) + c * 4;
    float w0 = wv[0], w1 = wv[1], w2 = wv[2], w3 = wv[3];
    float bias = (d == 0 ? cbF : cbB)[c];
    long rbase = (long)d * MT + (long)b * LL;
    const float* zin = g_zx + rbase * (long)DIP + DI + c;
    float* outp = g_xbc + (rbase + t0) * (long)CD + c;

    float in[CTT + 3];
    if (d == 0) {
#pragma unroll
        for (int j = 0; j < CTT + 3; j++) {
            int tt = t0 - 3 + j;
            in[j] = (tt >= 0) ? zin[(long)tt * DIP] : 0.f;
        }
#pragma unroll
        for (int i = 0; i < CTT; i++) {
            float a = bias;
            a = fmaf(w0, in[i], a); a = fmaf(w1, in[i+1], a);
            a = fmaf(w2, in[i+2], a); a = fmaf(w3, in[i+3], a);
            outp[(long)i * CD] = siluf(a);
        }
    } else {
#pragma unroll
        for (int j = 0; j < CTT + 3; j++) {
            int tt = t0 + j;
            in[j] = (tt < LL) ? zin[(long)tt * DIP] : 0.f;
        }
#pragma unroll
        for (int i = 0; i < CTT; i++) {
            float a = bias;
            a = fmaf(w3, in[i], a); a = fmaf(w2, in[i+1], a);
            a = fmaf(w1, in[i+2], a); a = fmaf(w0, in[i+3], a);
            outp[(long)i * CD] = siluf(a);
        }
    }
}

// ---------------- scan pass 1: chunk scans, cp.async smem double-buffer ----------------
__global__ __launch_bounds__(64)
void chunk_scan_k(const float* __restrict__ DpF, const float* __restrict__ DpB)
{
    int blk = blockIdx.x;
    int c   = blk & (NC - 1);
    int sid = blk >> 4;
    int d = sid >> 7, b = (sid >> 4) & 7, h = sid & 15;
    int p = threadIdx.x;

    __shared__ float sBC[2][8][36];   // [buf][j][B16,C16,dt,dA,pad]
    __shared__ float sX [2][8][64];   // [buf][j][p]
    float hs[16];
#pragma unroll
    for (int n = 0; n < 16; n++) hs[n] = 0.f;
    float dp = (d == 0 ? DpF : DpB)[h];
    long base0 = (long)d * MT + (long)b * LL;
    int s0 = c * CL;

    auto rowof = [&](int s) -> long {
        int t = (d == 0) ? s : (LL - 1 - s);
        return base0 + t;
    };
    auto loadgrp = [&](int gg, int buf) {
        {
            int j = p >> 3, seg = p & 7;
            long row = rowof(s0 + gg * 8 + j);
            cpa16(&sBC[buf][j][seg * 4], &g_xbc[row * (long)CD + DI + seg * 4]);
        }
#pragma unroll
        for (int it = 0; it < 2; it++) {
            int idx = p + it * 64;
            int j = idx >> 4, c4 = (idx & 15) << 2;
            long row = rowof(s0 + gg * 8 + j);
            cpa16(&sX[buf][j][c4], &g_xbc[row * (long)CD + h * HD + c4]);
        }
        if (p < 8) {
            long row = rowof(s0 + gg * 8 + p);
            cpa4(&sBC[buf][p][32], &g_dt[row * (long)NH + h]);
        } else if (p < 16) {
            long row = rowof(s0 + gg * 8 + (p - 8));
            cpa4(&sBC[buf][p - 8][33], &g_dA[row * (long)NH + h]);
        }
    };

    loadgrp(0, 0);
    CP_COMMIT();

    float P = 1.f;
    for (int gg = 0; gg < 16; gg++) {
        int buf = gg & 1;
        if (gg + 1 < 16) {
            loadgrp(gg + 1, buf ^ 1);
            CP_COMMIT();
            CP_WAIT(1);
        } else {
            CP_WAIT(0);
        }
        __syncthreads();
#pragma unroll
        for (int j = 0; j < 8; j++) {
            float xv  = sX[buf][j][p];
            float dtv = sBC[buf][j][32], dAv = sBC[buf][j][33];
            float coef = dtv * xv;
            float y = 0.f;
#pragma unroll
            for (int n = 0; n < 16; n++) {
                hs[n] = fmaf(hs[n], dAv, coef * sBC[buf][j][n]);
                y = fmaf(hs[n], sBC[buf][j][16 + n], y);
            }
            P *= dAv;
            int s = s0 + gg * 8 + j;
            g_y[rowof(s) * (long)DI + h * HD + p] = fmaf(dp, xv, y);
            if (p == 0) g_P[(size_t)sid * LL + s] = P;
        }
        __syncthreads();
    }

    float* Sp = g_S + (size_t)blk * (HD * 16) + p * 16;
#pragma unroll
    for (int n = 0; n < 16; n++) Sp[n] = hs[n];
}

// ---------------- scan pass 2: serial chunk-state propagation ----------------
__global__ __launch_bounds__(64)
void state_scan_k()
{
    int sid = blockIdx.x;
    int p = threadIdx.x;
    float hs[16];
#pragma unroll
    for (int n = 0; n < 16; n++) hs[n] = 0.f;

    for (int c = 0; c < NC; c++) {
        size_t off = ((size_t)(sid * NC + c)) * (HD * 16) + p * 16;
#pragma unroll
        for (int n = 0; n < 16; n++) g_hin[off + n] = hs[n];
        float Pt = g_P[(size_t)sid * LL + c * CL + CL - 1];
#pragma unroll
        for (int n = 0; n < 16; n++) hs[n] = fmaf(hs[n], Pt, g_S[off + n]);
    }
}

// ---------------- scan pass 3: y[s] += P[s] * (C[s] . h_in) ----------------
__global__ __launch_bounds__(64)
void fixup_k()
{
    int blk = blockIdx.x;
    int cm  = blk % (NC - 1);
    int sid = blk / (NC - 1);
    int c   = cm + 1;
    int d = sid >> 7, b = (sid >> 4) & 7, h = sid & 15;
    int p = threadIdx.x;
    long base0 = (long)d * MT + (long)b * LL;

    size_t off = ((size_t)(sid * NC + c)) * (HD * 16) + p * 16;
    float hin[16];
#pragma unroll
    for (int n = 0; n < 16; n++) hin[n] = g_hin[off + n];

    __shared__ float sC[4][16];
    __shared__ float sP[4];
    int s0 = c * CL;

    for (int i = 0; i < CL; i += 4) {
        {
            int tsub = p >> 4, n = p & 15;
            int s = s0 + i + tsub;
            int t = (d == 0) ? s : (LL - 1 - s);
            sC[tsub][n] = g_xbc[(base0 + t) * (long)CD + DI + 16 + n];
            if (n == 0) sP[tsub] = g_P[(size_t)sid * LL + s];
        }
        __syncthreads();
        float av[4];
#pragma unroll
        for (int j = 0; j < 4; j++) {
            float y = 0.f;
#pragma unroll
            for (int n = 0; n < 16; n++) y = fmaf(hin[n], sC[j][n], y);
            av[j] = y;
        }
#pragma unroll
        for (int j = 0; j < 4; j++) {
            int s = s0 + i + j;
            int t = (d == 0) ? s : (LL - 1 - s);
            long row = base0 + t;
            g_y[row * (long)DI + h * HD + p] += sP[j] * av[j];
        }
        __syncthreads();
    }
}

// ---------------- gated RMSNorm ----------------
__global__ __launch_bounds__(256)
void gnorm_k(const float* __restrict__ nwF, const float* __restrict__ nwB)
{
    long r = blockIdx.x;
    int  d = (int)(r / MT);
    const float* nw = (d == 0) ? nwF : nwB;
    const float* yp = g_y  + r * (long)DI;
    const float* zp = g_zx + r * (long)DIP;

    int i0 = threadIdx.x * 4;
    float v[4];
    float ss = 0.f;
#pragma unroll
    for (int j = 0; j < 4; j++) {
        float val = yp[i0 + j] * siluf(zp[i0 + j]);
        v[j] = val;
        ss = fmaf(val, val, ss);
    }
#pragma unroll
    for (int off = 16; off; off >>= 1) ss += __shfl_xor_sync(~0u, ss, off);
    __shared__ float ws[8];
    if ((threadIdx.x & 31) == 0) ws[threadIdx.x >> 5] = ss;
    __syncthreads();
    float tot = ws[0] + ws[1] + ws[2] + ws[3] + ws[4] + ws[5] + ws[6] + ws[7];
    float scale = rsqrtf(tot * (1.f / 1024.f) + 1e-5f);
#pragma unroll
    for (int j = 0; j < 4; j++)
        g_g[r * (long)DI + i0 + j] = v[j] * scale * nw[i0 + j];
}

// ---------------- launch ----------------
extern "C" void kernel_launch(void* const* d_in, const int* in_sizes, int n_in,
                              void* d_out, int out_size)
{
    const float* x    = (const float*)d_in[0];
    const float* ipwF = (const float*)d_in[1];
    const float* cwF  = (const float*)d_in[2];
    const float* cbF  = (const float*)d_in[3];
    const float* dbF  = (const float*)d_in[4];
    const float* alF  = (const float*)d_in[5];
    const float* dpF  = (const float*)d_in[6];
    const float* nwF  = (const float*)d_in[7];
    const float* opF  = (const float*)d_in[8];
    const float* ipwB = (const float*)d_in[9];
    const float* cwB  = (const float*)d_in[10];
    const float* cbB  = (const float*)d_in[11];
    const float* dbB  = (const float*)d_in[12];
    const float* alB  = (const float*)d_in[13];
    const float* dpB  = (const float*)d_in[14];
    const float* nwB  = (const float*)d_in[15];
    const float* opB  = (const float*)d_in[16];
    float* out = (float*)d_out;

    float *zx_d, *g_d;
    cudaGetSymbolAddress((void**)&zx_d, g_zx);
    cudaGetSymbolAddress((void**)&g_d,  g_g);

    cudaFuncSetAttribute((const void*)gemm_in,
                         cudaFuncAttributeMaxDynamicSharedMemorySize, GEMM_SMEM);
    cudaFuncSetAttribute((const void*)gemm_out,
                         cudaFuncAttributeMaxDynamicSharedMemorySize, GEMM_SMEM);

    // 1) in_proj both directions + fused dadt tail blocks (x = 17)
    gemm_in<<<dim3(18, 128, 2), 256, GEMM_SMEM>>>(x, ipwF, ipwB, zx_d,
                                                  dbF, alF, dbB, alB);

    // 2) depthwise conv + silu
    {
        long total = 2L * 8 * (LL / CTT) * CD;
        conv_silu_k<<<(unsigned)(total / 256), 256>>>(cwF, cbF, cwB, cbB);
    }

    // 3) chunked selective scan (cp.async staged)
    chunk_scan_k<<<NSCAN * NC, 64>>>(dpF, dpB);
    state_scan_k<<<NSCAN, 64>>>();
    fixup_k<<<NSCAN * (NC - 1), 64>>>();

    // 4) gated RMSNorm
    gnorm_k<<<2 * MT, 256>>>(nwF, nwB);

    // 5) out_proj: single GEMM, K-concat fwd+bwd
    gemm_out<<<dim3(4, 128), 256, GEMM_SMEM>>>(g_d, g_d + (size_t)MT * DI, opF, opB, out);
}

// round 11
// speedup vs baseline: 1.4058x; 1.2360x over previous
#include <cuda_runtime.h>
#include <cuda_fp16.h>
#include <math.h>
#include <stdint.h>

#define BB 8
#define LL 2048
#define DM 512
#define DI 1024
#define NH 16
#define HD 64
#define CD 1056
#define DIP 2096
#define MT (BB*LL)      // 16384 tokens
#define CL 128          // scan chunk length
#define NC (LL/CL)      // 16 chunks
#define NSCAN 256       // 2 dirs * 8 batch * 16 heads

// ---------------- scratch (static device globals; no allocation) ----------------
__device__ float  g_zx [2ull*MT*DIP];
__device__ float  g_xbc[2ull*MT*CD];
__device__ float  g_dt [2ull*MT*NH];
__device__ float  g_dA [2ull*MT*NH];
__device__ float  g_y  [2ull*MT*DI];
__device__ float  g_P  [(size_t)NSCAN*LL];
__device__ float  g_S  [(size_t)NSCAN*NC*HD*16];
__device__ float  g_hin[(size_t)NSCAN*NC*HD*16];
__device__ __half g_xh [(size_t)MT*DM];     // x in fp16
__device__ __half g_wih[2ull*DIP*DM];       // in_proj weights fp16
__device__ __half g_woh[2ull*DM*DI];        // out_proj weights fp16
__device__ __half g_gh [2ull*MT*DI];        // gated-norm output fp16

__device__ __forceinline__ float siluf(float v)     { return v / (1.f + expf(-v)); }
__device__ __forceinline__ float softplusf(float v) { return fmaxf(v, 0.f) + log1pf(expf(-fabsf(v))); }
__device__ __forceinline__ void mma16(float* c, const uint32_t* a, const uint32_t* b) {
    asm volatile(
        "mma.sync.aligned.m16n8k16.row.col.f32.f16.f16.f32 "
        "{%0,%1,%2,%3}, {%4,%5,%6,%7}, {%8,%9}, {%0,%1,%2,%3};"
        : "+f"(c[0]), "+f"(c[1]), "+f"(c[2]), "+f"(c[3])
        : "r"(a[0]), "r"(a[1]), "r"(a[2]), "r"(a[3]), "r"(b[0]), "r"(b[1]));
}
__device__ __forceinline__ void cpa16(const void* sp, const void* g) {
    uint32_t s = (uint32_t)__cvta_generic_to_shared(sp);
    asm volatile("cp.async.cg.shared.global [%0], [%1], 16;" :: "r"(s), "l"(g));
}
__device__ __forceinline__ void cpa16p(const void* sp, const void* g, bool pred) {
    uint32_t s = (uint32_t)__cvta_generic_to_shared(sp);
    int sz = pred ? 16 : 0;
    asm volatile("cp.async.cg.shared.global [%0], [%1], 16, %2;" :: "r"(s), "l"(g), "r"(sz));
}
__device__ __forceinline__ void cpa4(const void* sp, const void* g) {
    uint32_t s = (uint32_t)__cvta_generic_to_shared(sp);
    asm volatile("cp.async.ca.shared.global [%0], [%1], 4;" :: "r"(s), "l"(g));
}
#define CP_COMMIT() asm volatile("cp.async.commit_group;" ::: "memory")
#define CP_WAIT(n)  asm volatile("cp.async.wait_group %0;" :: "n"(n) : "memory")

// ---------------- fp32 -> fp16 conversion prep ----------------
__global__ __launch_bounds__(256)
void tohalf_k(const float4* __restrict__ s, __half2* __restrict__ d, int n4)
{
    int i = blockIdx.x * 256 + threadIdx.x;
    if (i < n4) {
        float4 v = s[i];
        d[2*i]   = __floats2half2_rn(v.x, v.y);
        d[2*i+1] = __floats2half2_rn(v.z, v.w);
    }
}

// ============================================================================
// fp16 GEMM (BM=128, BN=128, BK=32; 8 warps 2x4, warp tile 64x32), 3-stage.
// smem rows: 32 halfs data + pad -> stride 40 halfs (80B), conflict-free.
// Dynamic smem: 3 stages x (128+128) rows x 80B = 61440 B. 2 CTA/SM.
// ============================================================================
#define GEMM_SMEM 61440
#define ASMP(st,r,kh) ((const uint32_t*)(sAh + (((st)*128 + (r))*40 + (kh))))
#define BSMP(st,r,kh) ((const uint32_t*)(sBh + (((st)*128 + (r))*40 + (kh))))
#define ASMD(st,r,kh) ((void*)(sAh + (((st)*128 + (r))*40 + (kh))))
#define BSMD(st,r,kh) ((void*)(sBh + (((st)*128 + (r))*40 + (kh))))

#define GEMM_PROLOGUE \
    extern __shared__ __align__(16) char smraw[]; \
    __half* sAh = (__half*)smraw; \
    __half* sBh = (__half*)(smraw + 3*128*80); \
    const int tid  = threadIdx.x; \
    const int lane = tid & 31; \
    const int wid  = tid >> 5; \
    const int mw   = wid & 1; \
    const int nw   = wid >> 1; \
    const int g = lane >> 2; \
    const int q = lane & 3; \
    float acc[4][4][4]; \
    _Pragma("unroll") for (int i = 0; i < 4; i++) \
    _Pragma("unroll") for (int j = 0; j < 4; j++) \
    _Pragma("unroll") for (int r = 0; r < 4; r++) acc[i][j][r] = 0.f;

#define GEMM_COMPUTE(cur) \
    _Pragma("unroll") \
    for (int kk = 0; kk < 32; kk += 16) { \
        uint32_t af[4][4], bf[4][2]; \
        _Pragma("unroll") \
        for (int mt = 0; mt < 4; mt++) { \
            int row = mw * 64 + mt * 16 + g; \
            af[mt][0] = *ASMP(cur, row    , kk + 2*q    ); \
            af[mt][1] = *ASMP(cur, row + 8, kk + 2*q    ); \
            af[mt][2] = *ASMP(cur, row    , kk + 2*q + 8); \
            af[mt][3] = *ASMP(cur, row + 8, kk + 2*q + 8); \
        } \
        _Pragma("unroll") \
        for (int nt = 0; nt < 4; nt++) { \
            int col = nw * 32 + nt * 8 + g; \
            bf[nt][0] = *BSMP(cur, col, kk + 2*q    ); \
            bf[nt][1] = *BSMP(cur, col, kk + 2*q + 8); \
        } \
        _Pragma("unroll") \
        for (int mt = 0; mt < 4; mt++) \
        _Pragma("unroll") \
        for (int nt = 0; nt < 4; nt++) \
            mma16(acc[mt][nt], af[mt], bf[nt]); \
    }

#define GEMM_MAINLOOP(T) \
    load_tile(0, 0); CP_COMMIT(); \
    load_tile(1, 1); CP_COMMIT(); \
    load_tile(2, 2); CP_COMMIT(); \
    for (int kt = 0; kt < (T); kt++) { \
        const int cur = kt % 3; \
        if (kt + 2 < (T)) { CP_WAIT(2); } \
        else if (kt + 1 < (T)) { CP_WAIT(1); } \
        else { CP_WAIT(0); } \
        __syncthreads(); \
        GEMM_COMPUTE(cur) \
        __syncthreads(); \
        if (kt + 3 < (T)) { load_tile(kt + 3, cur); CP_COMMIT(); } \
    }

// ---------------- in_proj (+ fused dadt tail blocks): grid (18,128,2) ----------------
__global__ void __launch_bounds__(256, 2)
gemm_in(const __half* __restrict__ Ah, const __half* __restrict__ Bh0,
        const __half* __restrict__ Bh1, float* __restrict__ Cb,
        const float* __restrict__ x,
        const float* __restrict__ ipwF, const float* __restrict__ ipwB,
        const float* __restrict__ dbF,  const float* __restrict__ alF,
        const float* __restrict__ dbB,  const float* __restrict__ alB)
{
    if (blockIdx.x == 17) {
        // ---- dadt branch: exact-fp32 dt/dA for 128 tokens, dir = blockIdx.z ----
        extern __shared__ __align__(16) char smraw[];
        float (*sW)[512] = (float(*)[512])smraw;
        const int d  = blockIdx.z;
        const int tb = blockIdx.y;
        const int tid = threadIdx.x;
        const float* W = (d ? ipwB : ipwF) + (size_t)(DI + CD) * DM;
#pragma unroll
        for (int j = 0; j < 8; j++)
            ((float4*)&sW[0][0])[j * 256 + tid] = ((const float4*)W)[j * 256 + tid];
        __syncthreads();

        const int h = tid >> 4, l = tid & 15;
        const float db = (d ? dbB : dbF)[h];
        const float Av = -expf((d ? alB : alF)[h]);

        for (int tk = 0; tk < 128; tk++) {
            int token = tb * 128 + tk;
            const float4* xr = (const float4*)(x + (size_t)token * DM);
            const float4* wr = (const float4*)&sW[h][0];
            float s = 0.f;
#pragma unroll
            for (int j = 0; j < 8; j++) {
                float4 xv = xr[l + 16 * j];
                float4 wv = wr[l + 16 * j];
                s = fmaf(xv.x, wv.x, s); s = fmaf(xv.y, wv.y, s);
                s = fmaf(xv.z, wv.z, s); s = fmaf(xv.w, wv.w, s);
            }
            s += __shfl_xor_sync(~0u, s, 1);
            s += __shfl_xor_sync(~0u, s, 2);
            s += __shfl_xor_sync(~0u, s, 4);
            s += __shfl_xor_sync(~0u, s, 8);
            if (l == 0) {
                float dt = softplusf(s + db);
                size_t r = (size_t)d * MT + token;
                g_dt[r * NH + h] = dt;
                g_dA[r * NH + h] = expf(dt * Av);
            }
        }
        return;
    }

    const __half* B = blockIdx.z ? Bh1 : Bh0;
    float* C = Cb + (size_t)blockIdx.z * MT * DIP;
    const int m0 = blockIdx.y * 128, n0 = blockIdx.x * 128;
    const int N = DIP, K = DM;

    GEMM_PROLOGUE

    auto load_tile = [&](int kt, int buf) {
        const int k0 = kt << 5;
#pragma unroll
        for (int i = 0; i < 2; i++) {
            int id  = tid + (i << 8);
            int row = id >> 2;            // 0..127
            int seg = (id & 3) << 3;      // 0,8,16,24 halfs
            cpa16(ASMD(buf, row, seg), Ah + (size_t)(m0 + row) * K + k0 + seg);
            cpa16p(BSMD(buf, row, seg), B + (size_t)(n0 + row) * K + k0 + seg,
                   (n0 + row) < N);
        }
    };

    GEMM_MAINLOOP(K >> 5)

#pragma unroll
    for (int mt = 0; mt < 4; mt++) {
        int row = m0 + mw * 64 + mt * 16 + g;
#pragma unroll
        for (int nt = 0; nt < 4; nt++) {
            int n = n0 + nw * 32 + nt * 8 + q * 2;
            if (n < N) {
                *(float2*)(C + (size_t)row * DIP + n) =
                    make_float2(acc[mt][nt][0], acc[mt][nt][1]);
                *(float2*)(C + (size_t)(row + 8) * DIP + n) =
                    make_float2(acc[mt][nt][2], acc[mt][nt][3]);
            }
        }
    }
}

// ---------------- out_proj: K-concat of fwd+bwd (K=2048) -> single write ----------------
__global__ void __launch_bounds__(256, 2)
gemm_out(const __half* __restrict__ A0, const __half* __restrict__ A1,
         const __half* __restrict__ B0, const __half* __restrict__ B1,
         float* __restrict__ C)
{
    const int m0 = blockIdx.y * 128, n0 = blockIdx.x * 128;
    const int K = 2 * DI;

    GEMM_PROLOGUE

    auto load_tile = [&](int kt, int buf) {
        const int k0 = kt << 5;
        const __half* Ap; const __half* Bp; int kl;
        if (k0 < DI) { Ap = A0; Bp = B0; kl = k0; }
        else         { Ap = A1; Bp = B1; kl = k0 - DI; }
#pragma unroll
        for (int i = 0; i < 2; i++) {
            int id  = tid + (i << 8);
            int row = id >> 2;
            int seg = (id & 3) << 3;
            cpa16(ASMD(buf, row, seg), Ap + (size_t)(m0 + row) * DI + kl + seg);
            cpa16(BSMD(buf, row, seg), Bp + (size_t)(n0 + row) * DI + kl + seg);
        }
    };

    GEMM_MAINLOOP(K >> 5)

#pragma unroll
    for (int mt = 0; mt < 4; mt++) {
        int row = m0 + mw * 64 + mt * 16 + g;
#pragma unroll
        for (int nt = 0; nt < 4; nt++) {
            int n = n0 + nw * 32 + nt * 8 + q * 2;
            *(float2*)(C + (size_t)row * DM + n) =
                make_float2(acc[mt][nt][0], acc[mt][nt][1]);
            *(float2*)(C + (size_t)(row + 8) * DM + n) =
                make_float2(acc[mt][nt][2], acc[mt][nt][3]);
        }
    }
}

// ---------------- depthwise conv(4) + bias + SiLU, 8 outputs per thread ----------------
#define CTT 8
__global__ __launch_bounds__(256)
void conv_silu_k(const float* __restrict__ cwF, const float* __restrict__ cbF,
                 const float* __restrict__ cwB, const float* __restrict__ cbB)
{
    long idx = (long)blockIdx.x * 256 + threadIdx.x;
    int  c  = (int)(idx % CD);
    long q2 = idx / CD;
    int  tg = (int)(q2 & (LL / CTT - 1));
    int  bd = (int)(q2 >> 8);
    int  b  = bd & 7, d = bd >> 3;
    int  t0 = tg * CTT;

    const float* wv = (d == 0 ? cwF : cwB) + c * 4;
    float w0 = wv[0], w1 = wv[1], w2 = wv[2], w3 = wv[3];
    float bias = (d == 0 ? cbF : cbB)[c];
    long rbase = (long)d * MT + (long)b * LL;
    const float* zin = g_zx + rbase * (long)DIP + DI + c;
    float* outp = g_xbc + (rbase + t0) * (long)CD + c;

    float in[CTT + 3];
    if (d == 0) {
#pragma unroll
        for (int j = 0; j < CTT + 3; j++) {
            int tt = t0 - 3 + j;
            in[j] = (tt >= 0) ? zin[(long)tt * DIP] : 0.f;
        }
#pragma unroll
        for (int i = 0; i < CTT; i++) {
            float a = bias;
            a = fmaf(w0, in[i], a); a = fmaf(w1, in[i+1], a);
            a = fmaf(w2, in[i+2], a); a = fmaf(w3, in[i+3], a);
            outp[(long)i * CD] = siluf(a);
        }
    } else {
#pragma unroll
        for (int j = 0; j < CTT + 3; j++) {
            int tt = t0 + j;
            in[j] = (tt < LL) ? zin[(long)tt * DIP] : 0.f;
        }
#pragma unroll
        for (int i = 0; i < CTT; i++) {
            float a = bias;
            a = fmaf(w3, in[i], a); a = fmaf(w2, in[i+1], a);
            a = fmaf(w1, in[i+2], a); a = fmaf(w0, in[i+3], a);
            outp[(long)i * CD] = siluf(a);
        }
    }
}

// ---------------- scan pass 1: chunk scans, cp.async smem double-buffer ----------------
__global__ __launch_bounds__(64)
void chunk_scan_k(const float* __restrict__ DpF, const float* __restrict__ DpB)
{
    int blk = blockIdx.x;
    int c   = blk & (NC - 1);
    int sid = blk >> 4;
    int d = sid >> 7, b = (sid >> 4) & 7, h = sid & 15;
    int p = threadIdx.x;

    __shared__ float sBC[2][8][36];
    __shared__ float sX [2][8][64];
    float hs[16];
#pragma unroll
    for (int n = 0; n < 16; n++) hs[n] = 0.f;
    float dp = (d == 0 ? DpF : DpB)[h];
    long base0 = (long)d * MT + (long)b * LL;
    int s0 = c * CL;

    auto rowof = [&](int s) -> long {
        int t = (d == 0) ? s : (LL - 1 - s);
        return base0 + t;
    };
    auto loadgrp = [&](int gg, int buf) {
        {
            int j = p >> 3, seg = p & 7;
            long row = rowof(s0 + gg * 8 + j);
            cpa16(&sBC[buf][j][seg * 4], &g_xbc[row * (long)CD + DI + seg * 4]);
        }
#pragma unroll
        for (int it = 0; it < 2; it++) {
            int idx = p + it * 64;
            int j = idx >> 4, c4 = (idx & 15) << 2;
            long row = rowof(s0 + gg * 8 + j);
            cpa16(&sX[buf][j][c4], &g_xbc[row * (long)CD + h * HD + c4]);
        }
        if (p < 8) {
            long row = rowof(s0 + gg * 8 + p);
            cpa4(&sBC[buf][p][32], &g_dt[row * (long)NH + h]);
        } else if (p < 16) {
            long row = rowof(s0 + gg * 8 + (p - 8));
            cpa4(&sBC[buf][p - 8][33], &g_dA[row * (long)NH + h]);
        }
    };

    loadgrp(0, 0);
    CP_COMMIT();

    float P = 1.f;
    for (int gg = 0; gg < 16; gg++) {
        int buf = gg & 1;
        if (gg + 1 < 16) {
            loadgrp(gg + 1, buf ^ 1);
            CP_COMMIT();
            CP_WAIT(1);
        } else {
            CP_WAIT(0);
        }
        __syncthreads();
#pragma unroll
        for (int j = 0; j < 8; j++) {
            float xv  = sX[buf][j][p];
            float dtv = sBC[buf][j][32], dAv = sBC[buf][j][33];
            float coef = dtv * xv;
            float y = 0.f;
#pragma unroll
            for (int n = 0; n < 16; n++) {
                hs[n] = fmaf(hs[n], dAv, coef * sBC[buf][j][n]);
                y = fmaf(hs[n], sBC[buf][j][16 + n], y);
            }
            P *= dAv;
            int s = s0 + gg * 8 + j;
            g_y[rowof(s) * (long)DI + h * HD + p] = fmaf(dp, xv, y);
            if (p == 0) g_P[(size_t)sid * LL + s] = P;
        }
        __syncthreads();
    }

    float* Sp = g_S + (size_t)blk * (HD * 16) + p * 16;
#pragma unroll
    for (int n = 0; n < 16; n++) Sp[n] = hs[n];
}

// ---------------- scan pass 2: serial chunk-state propagation ----------------
__global__ __launch_bounds__(64)
void state_scan_k()
{
    int sid = blockIdx.x;
    int p = threadIdx.x;
    float hs[16];
#pragma unroll
    for (int n = 0; n < 16; n++) hs[n] = 0.f;

    for (int c = 0; c < NC; c++) {
        size_t off = ((size_t)(sid * NC + c)) * (HD * 16) + p * 16;
#pragma unroll
        for (int n = 0; n < 16; n++) g_hin[off + n] = hs[n];
        float Pt = g_P[(size_t)sid * LL + c * CL + CL - 1];
#pragma unroll
        for (int n = 0; n < 16; n++) hs[n] = fmaf(hs[n], Pt, g_S[off + n]);
    }
}

// ---------------- scan pass 3: y[s] += P[s] * (C[s] . h_in) ----------------
__global__ __launch_bounds__(64)
void fixup_k()
{
    int blk = blockIdx.x;
    int cm  = blk % (NC - 1);
    int sid = blk / (NC - 1);
    int c   = cm + 1;
    int d = sid >> 7, b = (sid >> 4) & 7, h = sid & 15;
    int p = threadIdx.x;
    long base0 = (long)d * MT + (long)b * LL;

    size_t off = ((size_t)(sid * NC + c)) * (HD * 16) + p * 16;
    float hin[16];
#pragma unroll
    for (int n = 0; n < 16; n++) hin[n] = g_hin[off + n];

    __shared__ float sC[4][16];
    __shared__ float sP[4];
    int s0 = c * CL;

    for (int i = 0; i < CL; i += 4) {
        {
            int tsub = p >> 4, n = p & 15;
            int s = s0 + i + tsub;
            int t = (d == 0) ? s : (LL - 1 - s);
            sC[tsub][n] = g_xbc[(base0 + t) * (long)CD + DI + 16 + n];
            if (n == 0) sP[tsub] = g_P[(size_t)sid * LL + s];
        }
        __syncthreads();
        float av[4];
#pragma unroll
        for (int j = 0; j < 4; j++) {
            float y = 0.f;
#pragma unroll
            for (int n = 0; n < 16; n++) y = fmaf(hin[n], sC[j][n], y);
            av[j] = y;
        }
#pragma unroll
        for (int j = 0; j < 4; j++) {
            int s = s0 + i + j;
            int t = (d == 0) ? s : (LL - 1 - s);
            long row = base0 + t;
            g_y[row * (long)DI + h * HD + p] += sP[j] * av[j];
        }
        __syncthreads();
    }
}

// ---------------- gated RMSNorm (writes fp16 for gemm_out) ----------------
__global__ __launch_bounds__(256)
void gnorm_k(const float* __restrict__ nwF, const float* __restrict__ nwB)
{
    long r = blockIdx.x;
    int  d = (int)(r / MT);
    const float* nw = (d == 0) ? nwF : nwB;
    const float* yp = g_y  + r * (long)DI;
    const float* zp = g_zx + r * (long)DIP;

    int i0 = threadIdx.x * 4;
    float v[4];
    float ss = 0.f;
#pragma unroll
    for (int j = 0; j < 4; j++) {
        float val = yp[i0 + j] * siluf(zp[i0 + j]);
        v[j] = val;
        ss = fmaf(val, val, ss);
    }
#pragma unroll
    for (int off = 16; off; off >>= 1) ss += __shfl_xor_sync(~0u, ss, off);
    __shared__ float ws[8];
    if ((threadIdx.x & 31) == 0) ws[threadIdx.x >> 5] = ss;
    __syncthreads();
    float tot = ws[0] + ws[1] + ws[2] + ws[3] + ws[4] + ws[5] + ws[6] + ws[7];
    float scale = rsqrtf(tot * (1.f / 1024.f) + 1e-5f);
    float o0 = v[0] * scale * nw[i0 + 0];
    float o1 = v[1] * scale * nw[i0 + 1];
    float o2 = v[2] * scale * nw[i0 + 2];
    float o3 = v[3] * scale * nw[i0 + 3];
    __half2* dst = (__half2*)&g_gh[r * (long)DI + i0];
    dst[0] = __floats2half2_rn(o0, o1);
    dst[1] = __floats2half2_rn(o2, o3);
}

// ---------------- launch ----------------
extern "C" void kernel_launch(void* const* d_in, const int* in_sizes, int n_in,
                              void* d_out, int out_size)
{
    const float* x    = (const float*)d_in[0];
    const float* ipwF = (const float*)d_in[1];
    const float* cwF  = (const float*)d_in[2];
    const float* cbF  = (const float*)d_in[3];
    const float* dbF  = (const float*)d_in[4];
    const float* alF  = (const float*)d_in[5];
    const float* dpF  = (const float*)d_in[6];
    const float* nwF  = (const float*)d_in[7];
    const float* opF  = (const float*)d_in[8];
    const float* ipwB = (const float*)d_in[9];
    const float* cwB  = (const float*)d_in[10];
    const float* cbB  = (const float*)d_in[11];
    const float* dbB  = (const float*)d_in[12];
    const float* alB  = (const float*)d_in[13];
    const float* dpB  = (const float*)d_in[14];
    const float* nwB  = (const float*)d_in[15];
    const float* opB  = (const float*)d_in[16];
    float* out = (float*)d_out;

    float *zx_d;
    __half *xh_d, *wih_d, *woh_d, *gh_d;
    cudaGetSymbolAddress((void**)&zx_d,  g_zx);
    cudaGetSymbolAddress((void**)&xh_d,  g_xh);
    cudaGetSymbolAddress((void**)&wih_d, g_wih);
    cudaGetSymbolAddress((void**)&woh_d, g_woh);
    cudaGetSymbolAddress((void**)&gh_d,  g_gh);

    cudaFuncSetAttribute((const void*)gemm_in,
                         cudaFuncAttributeMaxDynamicSharedMemorySize, GEMM_SMEM);
    cudaFuncSetAttribute((const void*)gemm_out,
                         cudaFuncAttributeMaxDynamicSharedMemorySize, GEMM_SMEM);

    // 0) fp32 -> fp16 conversions (x, in_proj weights, out_proj weights)
    {
        int n4;
        n4 = MT * DM / 4;
        tohalf_k<<<(n4 + 255) / 256, 256>>>((const float4*)x, (__half2*)xh_d, n4);
        n4 = DIP * DM / 4;
        tohalf_k<<<(n4 + 255) / 256, 256>>>((const float4*)ipwF, (__half2*)wih_d, n4);
        tohalf_k<<<(n4 + 255) / 256, 256>>>((const float4*)ipwB,
                                            (__half2*)(wih_d + (size_t)DIP * DM), n4);
        n4 = DM * DI / 4;
        tohalf_k<<<(n4 + 255) / 256, 256>>>((const float4*)opF, (__half2*)woh_d, n4);
        tohalf_k<<<(n4 + 255) / 256, 256>>>((const float4*)opB,
                                            (__half2*)(woh_d + (size_t)DM * DI), n4);
    }

    // 1) in_proj both directions + fused dadt tail blocks (x = 17), fp16 MMA
    gemm_in<<<dim3(18, 128, 2), 256, GEMM_SMEM>>>(
        xh_d, wih_d, wih_d + (size_t)DIP * DM, zx_d,
        x, ipwF, ipwB, dbF, alF, dbB, alB);

    // 2) depthwise conv + silu
    {
        long total = 2L * 8 * (LL / CTT) * CD;
        conv_silu_k<<<(unsigned)(total / 256), 256>>>(cwF, cbF, cwB, cbB);
    }

    // 3) chunked selective scan
    chunk_scan_k<<<NSCAN * NC, 64>>>(dpF, dpB);
    state_scan_k<<<NSCAN, 64>>>();
    fixup_k<<<NSCAN * (NC - 1), 64>>>();

    // 4) gated RMSNorm (fp16 output)
    gnorm_k<<<2 * MT, 256>>>(nwF, nwB);

    // 5) out_proj: single fp16 GEMM, K-concat fwd+bwd
    gemm_out<<<dim3(4, 128), 256, GEMM_SMEM>>>(
        gh_d, gh_d + (size_t)MT * DI,
        woh_d, woh_d + (size_t)DM * DI, out);
}

// round 12
// speedup vs baseline: 1.4388x; 1.0235x over previous
#include <cuda_runtime.h>
#include <cuda_fp16.h>
#include <math.h>
#include <stdint.h>

#define BB 8
#define LL 2048
#define DM 512
#define DI 1024
#define NH 16
#define HD 64
#define CD 1056
#define DIP 2096
#define MT (BB*LL)      // 16384 tokens
#define CL 128          // scan chunk length
#define NC (LL/CL)      // 16 chunks
#define NSCAN 256       // 2 dirs * 8 batch * 16 heads

// ---------------- scratch (static device globals; no allocation) ----------------
__device__ float  g_zx [2ull*MT*DIP];
__device__ float  g_xbc[2ull*MT*CD];
__device__ float  g_dt [2ull*MT*NH];
__device__ float  g_dA [2ull*MT*NH];
__device__ float  g_y  [2ull*MT*DI];
__device__ float  g_P  [(size_t)NSCAN*LL];
__device__ float  g_S  [(size_t)NSCAN*NC*HD*16];
__device__ float  g_hin[(size_t)NSCAN*NC*HD*16];
__device__ __half g_xh [(size_t)MT*DM];
__device__ __half g_wih[2ull*DIP*DM];
__device__ __half g_woh[2ull*DM*DI];
__device__ __half g_gh [2ull*MT*DI];

__device__ __forceinline__ float siluf(float v)     { return v / (1.f + expf(-v)); }
__device__ __forceinline__ float softplusf(float v) { return fmaxf(v, 0.f) + log1pf(expf(-fabsf(v))); }
__device__ __forceinline__ void mma16(float* c, const uint32_t* a, const uint32_t* b) {
    asm volatile(
        "mma.sync.aligned.m16n8k16.row.col.f32.f16.f16.f32 "
        "{%0,%1,%2,%3}, {%4,%5,%6,%7}, {%8,%9}, {%0,%1,%2,%3};"
        : "+f"(c[0]), "+f"(c[1]), "+f"(c[2]), "+f"(c[3])
        : "r"(a[0]), "r"(a[1]), "r"(a[2]), "r"(a[3]), "r"(b[0]), "r"(b[1]));
}
__device__ __forceinline__ void ldsm4(uint32_t* r, uint32_t addr) {
    asm volatile("ldmatrix.sync.aligned.m8n8.x4.shared.b16 {%0,%1,%2,%3}, [%4];"
        : "=r"(r[0]), "=r"(r[1]), "=r"(r[2]), "=r"(r[3]) : "r"(addr));
}
__device__ __forceinline__ uint32_t s2u32(const void* p) {
    return (uint32_t)__cvta_generic_to_shared(p);
}
__device__ __forceinline__ void cpa16(const void* sp, const void* g) {
    asm volatile("cp.async.cg.shared.global [%0], [%1], 16;" :: "r"(s2u32(sp)), "l"(g));
}
__device__ __forceinline__ void cpa16p(const void* sp, const void* g, bool pred) {
    int sz = pred ? 16 : 0;
    asm volatile("cp.async.cg.shared.global [%0], [%1], 16, %2;" :: "r"(s2u32(sp)), "l"(g), "r"(sz));
}
__device__ __forceinline__ void cpa4(const void* sp, const void* g) {
    asm volatile("cp.async.ca.shared.global [%0], [%1], 4;" :: "r"(s2u32(sp)), "l"(g));
}
#define CP_COMMIT() asm volatile("cp.async.commit_group;" ::: "memory")
#define CP_WAIT(n)  asm volatile("cp.async.wait_group %0;" :: "n"(n) : "memory")

// ---------------- fp32 -> fp16 conversion prep ----------------
__global__ __launch_bounds__(256)
void tohalf_k(const float4* __restrict__ s, __half2* __restrict__ d, int n4)
{
    int i = blockIdx.x * 256 + threadIdx.x;
    if (i < n4) {
        float4 v = s[i];
        d[2*i]   = __floats2half2_rn(v.x, v.y);
        d[2*i+1] = __floats2half2_rn(v.z, v.w);
    }
}

// ============================================================================
// fp16 GEMM (BM=128, BN=128, BK=32; 8 warps 2x4, warp tile 64x32), 3-stage,
// ldmatrix fragment loads. smem row stride 40 halfs (80B), conflict-free.
// Dynamic smem: 3 x (128+128) x 80B = 61440 B. 2 CTA/SM.
// ============================================================================
#define GEMM_SMEM 61440
#define ASMD(st,r,kh) ((void*)(sAh + (((st)*128 + (r))*40 + (kh))))
#define BSMD(st,r,kh) ((void*)(sBh + (((st)*128 + (r))*40 + (kh))))

#define GEMM_PROLOGUE \
    extern __shared__ __align__(16) char smraw[]; \
    __half* sAh = (__half*)smraw; \
    __half* sBh = (__half*)(smraw + 3*128*80); \
    const uint32_t sA32 = s2u32(sAh); \
    const uint32_t sB32 = s2u32(sBh); \
    const int tid  = threadIdx.x; \
    const int lane = tid & 31; \
    const int wid  = tid >> 5; \
    const int mw   = wid & 1; \
    const int nw   = wid >> 1; \
    const int g = lane >> 2; \
    const int q = lane & 3; \
    const int r8  = lane & 7; \
    const int sub = lane >> 3; \
    float acc[4][4][4]; \
    _Pragma("unroll") for (int i = 0; i < 4; i++) \
    _Pragma("unroll") for (int j = 0; j < 4; j++) \
    _Pragma("unroll") for (int r = 0; r < 4; r++) acc[i][j][r] = 0.f;

// A x4 tiles: t0=rows[0:8)k[0:8) t1=rows[8:16)k[0:8) t2=rows[0:8)k[8:16) t3=rows[8:16)k[8:16)
//   thread addr: row = row0 + (sub&1)*8 + r8 ; koff = kk + (sub>>1)*8
// B x4 tiles (two n8 groups): t0=n[0:8)k[0:8) t1=n[0:8)k[8:16) t2=n[8:16)k[0:8) t3=n[8:16)k[8:16)
//   thread addr: row = col0 + (sub>>1)*8 + r8 ; koff = kk + (sub&1)*8
#define GEMM_COMPUTE(cur) \
    { \
      const uint32_t abase = sA32 + (uint32_t)((((cur)*128 + mw*64 + (sub&1)*8 + r8)*40 + (sub>>1)*8)*2); \
      const uint32_t bbase = sB32 + (uint32_t)((((cur)*128 + nw*32 + (sub>>1)*8 + r8)*40 + (sub&1)*8)*2); \
      _Pragma("unroll") \
      for (int kk = 0; kk < 32; kk += 16) { \
        uint32_t af[4][4], bp0[4], bp1[4]; \
        _Pragma("unroll") \
        for (int mt = 0; mt < 4; mt++) ldsm4(af[mt], abase + mt*(16*80) + kk*2); \
        ldsm4(bp0, bbase + kk*2); \
        ldsm4(bp1, bbase + 16*80 + kk*2); \
        _Pragma("unroll") \
        for (int mt = 0; mt < 4; mt++) { \
            mma16(acc[mt][0], af[mt], bp0); \
            mma16(acc[mt][1], af[mt], bp0 + 2); \
            mma16(acc[mt][2], af[mt], bp1); \
            mma16(acc[mt][3], af[mt], bp1 + 2); \
        } \
      } \
    }

#define GEMM_MAINLOOP(T) \
    load_tile(0, 0); CP_COMMIT(); \
    load_tile(1, 1); CP_COMMIT(); \
    load_tile(2, 2); CP_COMMIT(); \
    for (int kt = 0; kt < (T); kt++) { \
        const int cur = kt % 3; \
        if (kt + 2 < (T)) { CP_WAIT(2); } \
        else if (kt + 1 < (T)) { CP_WAIT(1); } \
        else { CP_WAIT(0); } \
        __syncthreads(); \
        GEMM_COMPUTE(cur) \
        __syncthreads(); \
        if (kt + 3 < (T)) { load_tile(kt + 3, cur); CP_COMMIT(); } \
    }

// ---------------- in_proj (+ fused dadt tail blocks): grid (18,128,2) ----------------
__global__ void __launch_bounds__(256, 2)
gemm_in(const __half* __restrict__ Ah, const __half* __restrict__ Bh0,
        const __half* __restrict__ Bh1, float* __restrict__ Cb,
        const float* __restrict__ x,
        const float* __restrict__ ipwF, const float* __restrict__ ipwB,
        const float* __restrict__ dbF,  const float* __restrict__ alF,
        const float* __restrict__ dbB,  const float* __restrict__ alB)
{
    if (blockIdx.x == 17) {
        extern __shared__ __align__(16) char smraw[];
        float (*sW)[512] = (float(*)[512])smraw;
        const int d  = blockIdx.z;
        const int tb = blockIdx.y;
        const int tid = threadIdx.x;
        const float* W = (d ? ipwB : ipwF) + (size_t)(DI + CD) * DM;
#pragma unroll
        for (int j = 0; j < 8; j++)
            ((float4*)&sW[0][0])[j * 256 + tid] = ((const float4*)W)[j * 256 + tid];
        __syncthreads();

        const int h = tid >> 4, l = tid & 15;
        const float db = (d ? dbB : dbF)[h];
        const float Av = -expf((d ? alB : alF)[h]);

        for (int tk = 0; tk < 128; tk++) {
            int token = tb * 128 + tk;
            const float4* xr = (const float4*)(x + (size_t)token * DM);
            const float4* wr = (const float4*)&sW[h][0];
            float s = 0.f;
#pragma unroll
            for (int j = 0; j < 8; j++) {
                float4 xv = xr[l + 16 * j];
                float4 wv = wr[l + 16 * j];
                s = fmaf(xv.x, wv.x, s); s = fmaf(xv.y, wv.y, s);
                s = fmaf(xv.z, wv.z, s); s = fmaf(xv.w, wv.w, s);
            }
            s += __shfl_xor_sync(~0u, s, 1);
            s += __shfl_xor_sync(~0u, s, 2);
            s += __shfl_xor_sync(~0u, s, 4);
            s += __shfl_xor_sync(~0u, s, 8);
            if (l == 0) {
                float dt = softplusf(s + db);
                size_t r = (size_t)d * MT + token;
                g_dt[r * NH + h] = dt;
                g_dA[r * NH + h] = expf(dt * Av);
            }
        }
        return;
    }

    const __half* B = blockIdx.z ? Bh1 : Bh0;
    float* C = Cb + (size_t)blockIdx.z * MT * DIP;
    const int m0 = blockIdx.y * 128, n0 = blockIdx.x * 128;
    const int N = DIP, K = DM;

    GEMM_PROLOGUE

    auto load_tile = [&](int kt, int buf) {
        const int k0 = kt << 5;
#pragma unroll
        for (int i = 0; i < 2; i++) {
            int id  = tid + (i << 8);
            int row = id >> 2;
            int seg = (id & 3) << 3;
            cpa16(ASMD(buf, row, seg), Ah + (size_t)(m0 + row) * K + k0 + seg);
            cpa16p(BSMD(buf, row, seg), B + (size_t)(n0 + row) * K + k0 + seg,
                   (n0 + row) < N);
        }
    };

    GEMM_MAINLOOP(K >> 5)

#pragma unroll
    for (int mt = 0; mt < 4; mt++) {
        int row = m0 + mw * 64 + mt * 16 + g;
#pragma unroll
        for (int nt = 0; nt < 4; nt++) {
            int n = n0 + nw * 32 + nt * 8 + q * 2;
            if (n < N) {
                *(float2*)(C + (size_t)row * DIP + n) =
                    make_float2(acc[mt][nt][0], acc[mt][nt][1]);
                *(float2*)(C + (size_t)(row + 8) * DIP + n) =
                    make_float2(acc[mt][nt][2], acc[mt][nt][3]);
            }
        }
    }
}

// ---------------- out_proj: K-concat of fwd+bwd (K=2048) -> single write ----------------
__global__ void __launch_bounds__(256, 2)
gemm_out(const __half* __restrict__ A0, const __half* __restrict__ A1,
         const __half* __restrict__ B0, const __half* __restrict__ B1,
         float* __restrict__ C)
{
    const int m0 = blockIdx.y * 128, n0 = blockIdx.x * 128;
    const int K = 2 * DI;

    GEMM_PROLOGUE

    auto load_tile = [&](int kt, int buf) {
        const int k0 = kt << 5;
        const __half* Ap; const __half* Bp; int kl;
        if (k0 < DI) { Ap = A0; Bp = B0; kl = k0; }
        else         { Ap = A1; Bp = B1; kl = k0 - DI; }
#pragma unroll
        for (int i = 0; i < 2; i++) {
            int id  = tid + (i << 8);
            int row = id >> 2;
            int seg = (id & 3) << 3;
            cpa16(ASMD(buf, row, seg), Ap + (size_t)(m0 + row) * DI + kl + seg);
            cpa16(BSMD(buf, row, seg), Bp + (size_t)(n0 + row) * DI + kl + seg);
        }
    };

    GEMM_MAINLOOP(K >> 5)

#pragma unroll
    for (int mt = 0; mt < 4; mt++) {
        int row = m0 + mw * 64 + mt * 16 + g;
#pragma unroll
        for (int nt = 0; nt < 4; nt++) {
            int n = n0 + nw * 32 + nt * 8 + q * 2;
            *(float2*)(C + (size_t)row * DM + n) =
                make_float2(acc[mt][nt][0], acc[mt][nt][1]);
            *(float2*)(C + (size_t)(row + 8) * DM + n) =
                make_float2(acc[mt][nt][2], acc[mt][nt][3]);
        }
    }
}

// ---------------- depthwise conv(4) + bias + SiLU, 16 outputs per thread ----------------
#define CTT 16
__global__ __launch_bounds__(256)
void conv_silu_k(const float* __restrict__ cwF, const float* __restrict__ cbF,
                 const float* __restrict__ cwB, const float* __restrict__ cbB)
{
    long idx = (long)blockIdx.x * 256 + threadIdx.x;
    int  c  = (int)(idx % CD);
    long q2 = idx / CD;
    int  tg = (int)(q2 & (LL / CTT - 1));
    int  bd = (int)(q2 >> 7);          // LL/CTT = 128
    int  b  = bd & 7, d = bd >> 3;
    int  t0 = tg * CTT;

    const float* wv = (d == 0 ? cwF : cwB) + c * 4;
    float w0 = wv[0], w1 = wv[1], w2 = wv[2], w3 = wv[3];
    float bias = (d == 0 ? cbF : cbB)[c];
    long rbase = (long)d * MT + (long)b * LL;
    const float* zin = g_zx + rbase * (long)DIP + DI + c;
    float* outp = g_xbc + (rbase + t0) * (long)CD + c;

    float in[CTT + 3];
    if (d == 0) {
#pragma unroll
        for (int j = 0; j < CTT + 3; j++) {
            int tt = t0 - 3 + j;
            in[j] = (tt >= 0) ? zin[(long)tt * DIP] : 0.f;
        }
#pragma unroll
        for (int i = 0; i < CTT; i++) {
            float a = bias;
            a = fmaf(w0, in[i], a); a = fmaf(w1, in[i+1], a);
            a = fmaf(w2, in[i+2], a); a = fmaf(w3, in[i+3], a);
            outp[(long)i * CD] = siluf(a);
        }
    } else {
#pragma unroll
        for (int j = 0; j < CTT + 3; j++) {
            int tt = t0 + j;
            in[j] = (tt < LL) ? zin[(long)tt * DIP] : 0.f;
        }
#pragma unroll
        for (int i = 0; i < CTT; i++) {
            float a = bias;
            a = fmaf(w3, in[i], a); a = fmaf(w2, in[i+1], a);
            a = fmaf(w1, in[i+2], a); a = fmaf(w0, in[i+3], a);
            outp[(long)i * CD] = siluf(a);
        }
    }
}

// ---------------- scan pass 1: chunk scans, cp.async smem double-buffer ----------------
__global__ __launch_bounds__(64)
void chunk_scan_k(const float* __restrict__ DpF, const float* __restrict__ DpB)
{
    int blk = blockIdx.x;
    int c   = blk & (NC - 1);
    int sid = blk >> 4;
    int d = sid >> 7, b = (sid >> 4) & 7, h = sid & 15;
    int p = threadIdx.x;

    __shared__ float sBC[2][8][36];
    __shared__ float sX [2][8][64];
    float hs[16];
#pragma unroll
    for (int n = 0; n < 16; n++) hs[n] = 0.f;
    float dp = (d == 0 ? DpF : DpB)[h];
    long base0 = (long)d * MT + (long)b * LL;
    int s0 = c * CL;

    auto rowof = [&](int s) -> long {
        int t = (d == 0) ? s : (LL - 1 - s);
        return base0 + t;
    };
    auto loadgrp = [&](int gg, int buf) {
        {
            int j = p >> 3, seg = p & 7;
            long row = rowof(s0 + gg * 8 + j);
            cpa16(&sBC[buf][j][seg * 4], &g_xbc[row * (long)CD + DI + seg * 4]);
        }
#pragma unroll
        for (int it = 0; it < 2; it++) {
            int idx = p + it * 64;
            int j = idx >> 4, c4 = (idx & 15) << 2;
            long row = rowof(s0 + gg * 8 + j);
            cpa16(&sX[buf][j][c4], &g_xbc[row * (long)CD + h * HD + c4]);
        }
        if (p < 8) {
            long row = rowof(s0 + gg * 8 + p);
            cpa4(&sBC[buf][p][32], &g_dt[row * (long)NH + h]);
        } else if (p < 16) {
            long row = rowof(s0 + gg * 8 + (p - 8));
            cpa4(&sBC[buf][p - 8][33], &g_dA[row * (long)NH + h]);
        }
    };

    loadgrp(0, 0);
    CP_COMMIT();

    float P = 1.f;
    for (int gg = 0; gg < 16; gg++) {
        int buf = gg & 1;
        if (gg + 1 < 16) {
            loadgrp(gg + 1, buf ^ 1);
            CP_COMMIT();
            CP_WAIT(1);
        } else {
            CP_WAIT(0);
        }
        __syncthreads();
#pragma unroll
        for (int j = 0; j < 8; j++) {
            float xv  = sX[buf][j][p];
            float dtv = sBC[buf][j][32], dAv = sBC[buf][j][33];
            float coef = dtv * xv;
            float y = 0.f;
#pragma unroll
            for (int n = 0; n < 16; n++) {
                hs[n] = fmaf(hs[n], dAv, coef * sBC[buf][j][n]);
                y = fmaf(hs[n], sBC[buf][j][16 + n], y);
            }
            P *= dAv;
            int s = s0 + gg * 8 + j;
            g_y[rowof(s) * (long)DI + h * HD + p] = fmaf(dp, xv, y);
            if (p == 0) g_P[(size_t)sid * LL + s] = P;
        }
        __syncthreads();
    }

    float* Sp = g_S + (size_t)blk * (HD * 16) + p * 16;
#pragma unroll
    for (int n = 0; n < 16; n++) Sp[n] = hs[n];
}

// ---------------- scan pass 2: chunk-state propagation, prefetched ----------------
__global__ __launch_bounds__(64)
void state_scan_k()
{
    int sid = blockIdx.x;
    int p = threadIdx.x;
    __shared__ float sP[16];
    if (p < 16) sP[p] = g_P[(size_t)sid * LL + p * CL + CL - 1];
    __syncthreads();

    size_t base = (size_t)sid * NC * (HD * 16) + p * 16;
    float hs[16], nxt[16];
#pragma unroll
    for (int n = 0; n < 16; n++) { hs[n] = 0.f; nxt[n] = g_S[base + n]; }

    for (int c = 0; c < NC; c++) {
        size_t off = base + (size_t)c * (HD * 16);
#pragma unroll
        for (int n = 0; n < 16; n++) g_hin[off + n] = hs[n];
        float cur[16];
#pragma unroll
        for (int n = 0; n < 16; n++) cur[n] = nxt[n];
        if (c + 1 < NC) {
            size_t off2 = off + HD * 16;
#pragma unroll
            for (int n = 0; n < 16; n++) nxt[n] = g_S[off2 + n];
        }
        float Pt = sP[c];
#pragma unroll
        for (int n = 0; n < 16; n++) hs[n] = fmaf(hs[n], Pt, cur[n]);
    }
}

// ---------------- scan pass 3: y[s] += P[s] * (C[s] . h_in) ----------------
__global__ __launch_bounds__(64)
void fixup_k()
{
    int blk = blockIdx.x;
    int cm  = blk % (NC - 1);
    int sid = blk / (NC - 1);
    int c   = cm + 1;
    int d = sid >> 7, b = (sid >> 4) & 7, h = sid & 15;
    int p = threadIdx.x;
    long base0 = (long)d * MT + (long)b * LL;

    size_t off = ((size_t)(sid * NC + c)) * (HD * 16) + p * 16;
    float hin[16];
#pragma unroll
    for (int n = 0; n < 16; n++) hin[n] = g_hin[off + n];

    __shared__ float sC[4][16];
    __shared__ float sP[4];
    int s0 = c * CL;

    for (int i = 0; i < CL; i += 4) {
        {
            int tsub = p >> 4, n = p & 15;
            int s = s0 + i + tsub;
            int t = (d == 0) ? s : (LL - 1 - s);
            sC[tsub][n] = g_xbc[(base0 + t) * (long)CD + DI + 16 + n];
            if (n == 0) sP[tsub] = g_P[(size_t)sid * LL + s];
        }
        __syncthreads();
        float av[4];
#pragma unroll
        for (int j = 0; j < 4; j++) {
            float y = 0.f;
#pragma unroll
            for (int n = 0; n < 16; n++) y = fmaf(hin[n], sC[j][n], y);
            av[j] = y;
        }
#pragma unroll
        for (int j = 0; j < 4; j++) {
            int s = s0 + i + j;
            int t = (d == 0) ? s : (LL - 1 - s);
            long row = base0 + t;
            g_y[row * (long)DI + h * HD + p] += sP[j] * av[j];
        }
        __syncthreads();
    }
}

// ---------------- gated RMSNorm (writes fp16 for gemm_out) ----------------
__global__ __launch_bounds__(256)
void gnorm_k(const float* __restrict__ nwF, const float* __restrict__ nwB)
{
    long r = blockIdx.x;
    int  d = (int)(r / MT);
    const float* nw = (d == 0) ? nwF : nwB;
    const float* yp = g_y  + r * (long)DI;
    const float* zp = g_zx + r * (long)DIP;

    int i0 = threadIdx.x * 4;
    float v[4];
    float ss = 0.f;
#pragma unroll
    for (int j = 0; j < 4; j++) {
        float val = yp[i0 + j] * siluf(zp[i0 + j]);
        v[j] = val;
        ss = fmaf(val, val, ss);
    }
#pragma unroll
    for (int off = 16; off; off >>= 1) ss += __shfl_xor_sync(~0u, ss, off);
    __shared__ float ws[8];
    if ((threadIdx.x & 31) == 0) ws[threadIdx.x >> 5] = ss;
    __syncthreads();
    float tot = ws[0] + ws[1] + ws[2] + ws[3] + ws[4] + ws[5] + ws[6] + ws[7];
    float scale = rsqrtf(tot * (1.f / 1024.f) + 1e-5f);
    float o0 = v[0] * scale * nw[i0 + 0];
    float o1 = v[1] * scale * nw[i0 + 1];
    float o2 = v[2] * scale * nw[i0 + 2];
    float o3 = v[3] * scale * nw[i0 + 3];
    __half2* dst = (__half2*)&g_gh[r * (long)DI + i0];
    dst[0] = __floats2half2_rn(o0, o1);
    dst[1] = __floats2half2_rn(o2, o3);
}

// ---------------- launch ----------------
extern "C" void kernel_launch(void* const* d_in, const int* in_sizes, int n_in,
                              void* d_out, int out_size)
{
    const float* x    = (const float*)d_in[0];
    const float* ipwF = (const float*)d_in[1];
    const float* cwF  = (const float*)d_in[2];
    const float* cbF  = (const float*)d_in[3];
    const float* dbF  = (const float*)d_in[4];
    const float* alF  = (const float*)d_in[5];
    const float* dpF  = (const float*)d_in[6];
    const float* nwF  = (const float*)d_in[7];
    const float* opF  = (const float*)d_in[8];
    const float* ipwB = (const float*)d_in[9];
    const float* cwB  = (const float*)d_in[10];
    const float* cbB  = (const float*)d_in[11];
    const float* dbB  = (const float*)d_in[12];
    const float* alB  = (const float*)d_in[13];
    const float* dpB  = (const float*)d_in[14];
    const float* nwB  = (const float*)d_in[15];
    const float* opB  = (const float*)d_in[16];
    float* out = (float*)d_out;

    float *zx_d;
    __half *xh_d, *wih_d, *woh_d, *gh_d;
    cudaGetSymbolAddress((void**)&zx_d,  g_zx);
    cudaGetSymbolAddress((void**)&xh_d,  g_xh);
    cudaGetSymbolAddress((void**)&wih_d, g_wih);
    cudaGetSymbolAddress((void**)&woh_d, g_woh);
    cudaGetSymbolAddress((void**)&gh_d,  g_gh);

    cudaFuncSetAttribute((const void*)gemm_in,
                         cudaFuncAttributeMaxDynamicSharedMemorySize, GEMM_SMEM);
    cudaFuncSetAttribute((const void*)gemm_out,
                         cudaFuncAttributeMaxDynamicSharedMemorySize, GEMM_SMEM);

    // 0) fp32 -> fp16 conversions
    {
        int n4;
        n4 = MT * DM / 4;
        tohalf_k<<<(n4 + 255) / 256, 256>>>((const float4*)x, (__half2*)xh_d, n4);
        n4 = DIP * DM / 4;
        tohalf_k<<<(n4 + 255) / 256, 256>>>((const float4*)ipwF, (__half2*)wih_d, n4);
        tohalf_k<<<(n4 + 255) / 256, 256>>>((const float4*)ipwB,
                                            (__half2*)(wih_d + (size_t)DIP * DM), n4);
        n4 = DM * DI / 4;
        tohalf_k<<<(n4 + 255) / 256, 256>>>((const float4*)opF, (__half2*)woh_d, n4);
        tohalf_k<<<(n4 + 255) / 256, 256>>>((const float4*)opB,
                                            (__half2*)(woh_d + (size_t)DM * DI), n4);
    }

    // 1) in_proj both directions + fused dadt tail blocks (x = 17)
    gemm_in<<<dim3(18, 128, 2), 256, GEMM_SMEM>>>(
        xh_d, wih_d, wih_d + (size_t)DIP * DM, zx_d,
        x, ipwF, ipwB, dbF, alF, dbB, alB);

    // 2) depthwise conv + silu
    {
        long total = 2L * 8 * (LL / CTT) * CD;
        conv_silu_k<<<(unsigned)(total / 256), 256>>>(cwF, cbF, cwB, cbB);
    }

    // 3) chunked selective scan
    chunk_scan_k<<<NSCAN * NC, 64>>>(dpF, dpB);
    state_scan_k<<<NSCAN, 64>>>();
    fixup_k<<<NSCAN * (NC - 1), 64>>>();

    // 4) gated RMSNorm (fp16 output)
    gnorm_k<<<2 * MT, 256>>>(nwF, nwB);

    // 5) out_proj: single fp16 GEMM, K-concat fwd+bwd
    gemm_out<<<dim3(4, 128), 256, GEMM_SMEM>>>(
        gh_d, gh_d + (size_t)MT * DI,
        woh_d, woh_d + (size_t)DM * DI, out);
}

// round 13
// speedup vs baseline: 1.5310x; 1.0641x over previous
#include <cuda_runtime.h>
#include <cuda_fp16.h>
#include <math.h>
#include <stdint.h>

#define BB 8
#define LL 2048
#define DM 512
#define DI 1024
#define NH 16
#define HD 64
#define CD 1056
#define DIP 2096
#define MT (BB*LL)      // 16384 tokens
#define CL 128          // scan chunk length
#define NC (LL/CL)      // 16 chunks
#define NSCAN 256       // 2 dirs * 8 batch * 16 heads

// ---------------- scratch (static device globals; no allocation) ----------------
__device__ __half g_zxh[2ull*MT*DIP];       // in_proj output in fp16
__device__ float  g_xbc[2ull*MT*CD];
__device__ float  g_dt [2ull*MT*NH];
__device__ float  g_dA [2ull*MT*NH];
__device__ float  g_y  [2ull*MT*DI];
__device__ float  g_P  [(size_t)NSCAN*LL];
__device__ float  g_S  [(size_t)NSCAN*NC*HD*16];
__device__ float  g_hin[(size_t)NSCAN*NC*HD*16];
__device__ __half g_xh [(size_t)MT*DM];
__device__ __half g_wih[2ull*DIP*DM];
__device__ __half g_woh[2ull*DM*DI];
__device__ __half g_gh [2ull*MT*DI];

__device__ __forceinline__ float siluf(float v)     { return v / (1.f + expf(-v)); }
__device__ __forceinline__ float softplusf(float v) { return fmaxf(v, 0.f) + log1pf(expf(-fabsf(v))); }
__device__ __forceinline__ void mma16(float* c, const uint32_t* a, const uint32_t* b) {
    asm volatile(
        "mma.sync.aligned.m16n8k16.row.col.f32.f16.f16.f32 "
        "{%0,%1,%2,%3}, {%4,%5,%6,%7}, {%8,%9}, {%0,%1,%2,%3};"
        : "+f"(c[0]), "+f"(c[1]), "+f"(c[2]), "+f"(c[3])
        : "r"(a[0]), "r"(a[1]), "r"(a[2]), "r"(a[3]), "r"(b[0]), "r"(b[1]));
}
__device__ __forceinline__ void ldsm4(uint32_t* r, uint32_t addr) {
    asm volatile("ldmatrix.sync.aligned.m8n8.x4.shared.b16 {%0,%1,%2,%3}, [%4];"
        : "=r"(r[0]), "=r"(r[1]), "=r"(r[2]), "=r"(r[3]) : "r"(addr));
}
__device__ __forceinline__ uint32_t s2u32(const void* p) {
    return (uint32_t)__cvta_generic_to_shared(p);
}
__device__ __forceinline__ void cpa16(const void* sp, const void* g) {
    asm volatile("cp.async.cg.shared.global [%0], [%1], 16;" :: "r"(s2u32(sp)), "l"(g));
}
__device__ __forceinline__ void cpa16p(const void* sp, const void* g, bool pred) {
    int sz = pred ? 16 : 0;
    asm volatile("cp.async.cg.shared.global [%0], [%1], 16, %2;" :: "r"(s2u32(sp)), "l"(g), "r"(sz));
}
__device__ __forceinline__ void cpa4(const void* sp, const void* g) {
    asm volatile("cp.async.ca.shared.global [%0], [%1], 4;" :: "r"(s2u32(sp)), "l"(g));
}
#define CP_COMMIT() asm volatile("cp.async.commit_group;" ::: "memory")
#define CP_WAIT(n)  asm volatile("cp.async.wait_group %0;" :: "n"(n) : "memory")

// ---------------- fp32 -> fp16 conversion prep (single launch, 5 regions) ----------------
#define N4_X  (MT*DM/4)
#define N4_WI (DIP*DM/4)
#define N4_WO (DM*DI/4)
__global__ __launch_bounds__(256)
void tohalf_all(const float4* __restrict__ x,
                const float4* __restrict__ wF, const float4* __restrict__ wB,
                const float4* __restrict__ oF, const float4* __restrict__ oB,
                __half2* __restrict__ xh, __half2* __restrict__ wih,
                __half2* __restrict__ woh)
{
    int i = blockIdx.x * 256 + threadIdx.x;
    const float4* s; __half2* d; int li;
    if (i < N4_X)                    { s = x;  d = xh;                li = i; }
    else if (i < N4_X + N4_WI)       { s = wF; d = wih;               li = i - N4_X; }
    else if (i < N4_X + 2*N4_WI)     { s = wB; d = wih + N4_WI*2;     li = i - N4_X - N4_WI; }
    else if (i < N4_X + 2*N4_WI + N4_WO) { s = oF; d = woh;           li = i - N4_X - 2*N4_WI; }
    else if (i < N4_X + 2*N4_WI + 2*N4_WO) { s = oB; d = woh + N4_WO*2; li = i - N4_X - 2*N4_WI - N4_WO; }
    else return;
    float4 v = s[li];
    d[2*li]   = __floats2half2_rn(v.x, v.y);
    d[2*li+1] = __floats2half2_rn(v.z, v.w);
}

// ============================================================================
// fp16 GEMM (BM=128, BN=128, BK=32; 8 warps 2x4, warp tile 64x32), 3-stage,
// ldmatrix fragment loads. smem row stride 40 halfs (80B), conflict-free.
// Dynamic smem: 3 x (128+128) x 80B = 61440 B. 2 CTA/SM.
// ============================================================================
#define GEMM_SMEM 61440
#define ASMD(st,r,kh) ((void*)(sAh + (((st)*128 + (r))*40 + (kh))))
#define BSMD(st,r,kh) ((void*)(sBh + (((st)*128 + (r))*40 + (kh))))

#define GEMM_PROLOGUE \
    extern __shared__ __align__(16) char smraw[]; \
    __half* sAh = (__half*)smraw; \
    __half* sBh = (__half*)(smraw + 3*128*80); \
    const uint32_t sA32 = s2u32(sAh); \
    const uint32_t sB32 = s2u32(sBh); \
    const int tid  = threadIdx.x; \
    const int lane = tid & 31; \
    const int wid  = tid >> 5; \
    const int mw   = wid & 1; \
    const int nw   = wid >> 1; \
    const int g = lane >> 2; \
    const int q = lane & 3; \
    const int r8  = lane & 7; \
    const int sub = lane >> 3; \
    float acc[4][4][4]; \
    _Pragma("unroll") for (int i = 0; i < 4; i++) \
    _Pragma("unroll") for (int j = 0; j < 4; j++) \
    _Pragma("unroll") for (int r = 0; r < 4; r++) acc[i][j][r] = 0.f;

#define GEMM_COMPUTE(cur) \
    { \
      const uint32_t abase = sA32 + (uint32_t)((((cur)*128 + mw*64 + (sub&1)*8 + r8)*40 + (sub>>1)*8)*2); \
      const uint32_t bbase = sB32 + (uint32_t)((((cur)*128 + nw*32 + (sub>>1)*8 + r8)*40 + (sub&1)*8)*2); \
      _Pragma("unroll") \
      for (int kk = 0; kk < 32; kk += 16) { \
        uint32_t af[4][4], bp0[4], bp1[4]; \
        _Pragma("unroll") \
        for (int mt = 0; mt < 4; mt++) ldsm4(af[mt], abase + mt*(16*80) + kk*2); \
        ldsm4(bp0, bbase + kk*2); \
        ldsm4(bp1, bbase + 16*80 + kk*2); \
        _Pragma("unroll") \
        for (int mt = 0; mt < 4; mt++) { \
            mma16(acc[mt][0], af[mt], bp0); \
            mma16(acc[mt][1], af[mt], bp0 + 2); \
            mma16(acc[mt][2], af[mt], bp1); \
            mma16(acc[mt][3], af[mt], bp1 + 2); \
        } \
      } \
    }

#define GEMM_MAINLOOP(T) \
    load_tile(0, 0); CP_COMMIT(); \
    load_tile(1, 1); CP_COMMIT(); \
    load_tile(2, 2); CP_COMMIT(); \
    for (int kt = 0; kt < (T); kt++) { \
        const int cur = kt % 3; \
        if (kt + 2 < (T)) { CP_WAIT(2); } \
        else if (kt + 1 < (T)) { CP_WAIT(1); } \
        else { CP_WAIT(0); } \
        __syncthreads(); \
        GEMM_COMPUTE(cur) \
        __syncthreads(); \
        if (kt + 3 < (T)) { load_tile(kt + 3, cur); CP_COMMIT(); } \
    }

// ---------------- in_proj (+ fused dadt tail blocks): grid (18,128,2) ----------------
__global__ void __launch_bounds__(256, 2)
gemm_in(const __half* __restrict__ Ah, const __half* __restrict__ Bh0,
        const __half* __restrict__ Bh1, __half* __restrict__ Cb,
        const float* __restrict__ x,
        const float* __restrict__ ipwF, const float* __restrict__ ipwB,
        const float* __restrict__ dbF,  const float* __restrict__ alF,
        const float* __restrict__ dbB,  const float* __restrict__ alB)
{
    if (blockIdx.x == 17) {
        extern __shared__ __align__(16) char smraw[];
        float (*sW)[512] = (float(*)[512])smraw;
        const int d  = blockIdx.z;
        const int tb = blockIdx.y;
        const int tid = threadIdx.x;
        const float* W = (d ? ipwB : ipwF) + (size_t)(DI + CD) * DM;
#pragma unroll
        for (int j = 0; j < 8; j++)
            ((float4*)&sW[0][0])[j * 256 + tid] = ((const float4*)W)[j * 256 + tid];
        __syncthreads();

        const int h = tid >> 4, l = tid & 15;
        const float db = (d ? dbB : dbF)[h];
        const float Av = -expf((d ? alB : alF)[h]);

        for (int tk = 0; tk < 128; tk++) {
            int token = tb * 128 + tk;
            const float4* xr = (const float4*)(x + (size_t)token * DM);
            const float4* wr = (const float4*)&sW[h][0];
            float s = 0.f;
#pragma unroll
            for (int j = 0; j < 8; j++) {
                float4 xv = xr[l + 16 * j];
                float4 wv = wr[l + 16 * j];
                s = fmaf(xv.x, wv.x, s); s = fmaf(xv.y, wv.y, s);
                s = fmaf(xv.z, wv.z, s); s = fmaf(xv.w, wv.w, s);
            }
            s += __shfl_xor_sync(~0u, s, 1);
            s += __shfl_xor_sync(~0u, s, 2);
            s += __shfl_xor_sync(~0u, s, 4);
            s += __shfl_xor_sync(~0u, s, 8);
            if (l == 0) {
                float dt = softplusf(s + db);
                size_t r = (size_t)d * MT + token;
                g_dt[r * NH + h] = dt;
                g_dA[r * NH + h] = expf(dt * Av);
            }
        }
        return;
    }

    const __half* B = blockIdx.z ? Bh1 : Bh0;
    __half* C = Cb + (size_t)blockIdx.z * MT * DIP;
    const int m0 = blockIdx.y * 128, n0 = blockIdx.x * 128;
    const int N = DIP, K = DM;

    GEMM_PROLOGUE

    auto load_tile = [&](int kt, int buf) {
        const int k0 = kt << 5;
#pragma unroll
        for (int i = 0; i < 2; i++) {
            int id  = tid + (i << 8);
            int row = id >> 2;
            int seg = (id & 3) << 3;
            cpa16(ASMD(buf, row, seg), Ah + (size_t)(m0 + row) * K + k0 + seg);
            cpa16p(BSMD(buf, row, seg), B + (size_t)(n0 + row) * K + k0 + seg,
                   (n0 + row) < N);
        }
    };

    GEMM_MAINLOOP(K >> 5)

#pragma unroll
    for (int mt = 0; mt < 4; mt++) {
        int row = m0 + mw * 64 + mt * 16 + g;
#pragma unroll
        for (int nt = 0; nt < 4; nt++) {
            int n = n0 + nw * 32 + nt * 8 + q * 2;
            if (n < N) {
                *(__half2*)(C + (size_t)row * DIP + n) =
                    __floats2half2_rn(acc[mt][nt][0], acc[mt][nt][1]);
                *(__half2*)(C + (size_t)(row + 8) * DIP + n) =
                    __floats2half2_rn(acc[mt][nt][2], acc[mt][nt][3]);
            }
        }
    }
}

// ---------------- out_proj: K-concat of fwd+bwd (K=2048) -> single write ----------------
__global__ void __launch_bounds__(256, 2)
gemm_out(const __half* __restrict__ A0, const __half* __restrict__ A1,
         const __half* __restrict__ B0, const __half* __restrict__ B1,
         float* __restrict__ C)
{
    const int m0 = blockIdx.y * 128, n0 = blockIdx.x * 128;
    const int K = 2 * DI;

    GEMM_PROLOGUE

    auto load_tile = [&](int kt, int buf) {
        const int k0 = kt << 5;
        const __half* Ap; const __half* Bp; int kl;
        if (k0 < DI) { Ap = A0; Bp = B0; kl = k0; }
        else         { Ap = A1; Bp = B1; kl = k0 - DI; }
#pragma unroll
        for (int i = 0; i < 2; i++) {
            int id  = tid + (i << 8);
            int row = id >> 2;
            int seg = (id & 3) << 3;
            cpa16(ASMD(buf, row, seg), Ap + (size_t)(m0 + row) * DI + kl + seg);
            cpa16(BSMD(buf, row, seg), Bp + (size_t)(n0 + row) * DI + kl + seg);
        }
    };

    GEMM_MAINLOOP(K >> 5)

#pragma unroll
    for (int mt = 0; mt < 4; mt++) {
        int row = m0 + mw * 64 + mt * 16 + g;
#pragma unroll
        for (int nt = 0; nt < 4; nt++) {
            int n = n0 + nw * 32 + nt * 8 + q * 2;
            *(float2*)(C + (size_t)row * DM + n) =
                make_float2(acc[mt][nt][0], acc[mt][nt][1]);
            *(float2*)(C + (size_t)(row + 8) * DM + n) =
                make_float2(acc[mt][nt][2], acc[mt][nt][3]);
        }
    }
}

// ---------------- depthwise conv(4) + bias + SiLU, 16 outputs per thread ----------------
#define CTT 16
__global__ __launch_bounds__(256)
void conv_silu_k(const float* __restrict__ cwF, const float* __restrict__ cbF,
                 const float* __restrict__ cwB, const float* __restrict__ cbB)
{
    long idx = (long)blockIdx.x * 256 + threadIdx.x;
    int  c  = (int)(idx % CD);
    long q2 = idx / CD;
    int  tg = (int)(q2 & (LL / CTT - 1));
    int  bd = (int)(q2 >> 7);          // LL/CTT = 128
    int  b  = bd & 7, d = bd >> 3;
    int  t0 = tg * CTT;

    const float* wv = (d == 0 ? cwF : cwB) + c * 4;
    float w0 = wv[0], w1 = wv[1], w2 = wv[2], w3 = wv[3];
    float bias = (d == 0 ? cbF : cbB)[c];
    long rbase = (long)d * MT + (long)b * LL;
    const __half* zin = g_zxh + rbase * (long)DIP + DI + c;
    float* outp = g_xbc + (rbase + t0) * (long)CD + c;

    float in[CTT + 3];
    if (d == 0) {
#pragma unroll
        for (int j = 0; j < CTT + 3; j++) {
            int tt = t0 - 3 + j;
            in[j] = (tt >= 0) ? __half2float(zin[(long)tt * DIP]) : 0.f;
        }
#pragma unroll
        for (int i = 0; i < CTT; i++) {
            float a = bias;
            a = fmaf(w0, in[i], a); a = fmaf(w1, in[i+1], a);
            a = fmaf(w2, in[i+2], a); a = fmaf(w3, in[i+3], a);
            outp[(long)i * CD] = siluf(a);
        }
    } else {
#pragma unroll
        for (int j = 0; j < CTT + 3; j++) {
            int tt = t0 + j;
            in[j] = (tt < LL) ? __half2float(zin[(long)tt * DIP]) : 0.f;
        }
#pragma unroll
        for (int i = 0; i < CTT; i++) {
            float a = bias;
            a = fmaf(w3, in[i], a); a = fmaf(w2, in[i+1], a);
            a = fmaf(w1, in[i+2], a); a = fmaf(w0, in[i+3], a);
            outp[(long)i * CD] = siluf(a);
        }
    }
}

// ---------------- scan pass 1: chunk scans, cp.async smem double-buffer ----------------
__global__ __launch_bounds__(64)
void chunk_scan_k(const float* __restrict__ DpF, const float* __restrict__ DpB)
{
    int blk = blockIdx.x;
    int c   = blk & (NC - 1);
    int sid = blk >> 4;
    int d = sid >> 7, b = (sid >> 4) & 7, h = sid & 15;
    int p = threadIdx.x;

    __shared__ float sBC[2][8][36];
    __shared__ float sX [2][8][64];
    float hs[16];
#pragma unroll
    for (int n = 0; n < 16; n++) hs[n] = 0.f;
    float dp = (d == 0 ? DpF : DpB)[h];
    long base0 = (long)d * MT + (long)b * LL;
    int s0 = c * CL;

    auto rowof = [&](int s) -> long {
        int t = (d == 0) ? s : (LL - 1 - s);
        return base0 + t;
    };
    auto loadgrp = [&](int gg, int buf) {
        {
            int j = p >> 3, seg = p & 7;
            long row = rowof(s0 + gg * 8 + j);
            cpa16(&sBC[buf][j][seg * 4], &g_xbc[row * (long)CD + DI + seg * 4]);
        }
#pragma unroll
        for (int it = 0; it < 2; it++) {
            int idx = p + it * 64;
            int j = idx >> 4, c4 = (idx & 15) << 2;
            long row = rowof(s0 + gg * 8 + j);
            cpa16(&sX[buf][j][c4], &g_xbc[row * (long)CD + h * HD + c4]);
        }
        if (p < 8) {
            long row = rowof(s0 + gg * 8 + p);
            cpa4(&sBC[buf][p][32], &g_dt[row * (long)NH + h]);
        } else if (p < 16) {
            long row = rowof(s0 + gg * 8 + (p - 8));
            cpa4(&sBC[buf][p - 8][33], &g_dA[row * (long)NH + h]);
        }
    };

    loadgrp(0, 0);
    CP_COMMIT();

    float P = 1.f;
    for (int gg = 0; gg < 16; gg++) {
        int buf = gg & 1;
        if (gg + 1 < 16) {
            loadgrp(gg + 1, buf ^ 1);
            CP_COMMIT();
            CP_WAIT(1);
        } else {
            CP_WAIT(0);
        }
        __syncthreads();
#pragma unroll
        for (int j = 0; j < 8; j++) {
            float xv  = sX[buf][j][p];
            float dtv = sBC[buf][j][32], dAv = sBC[buf][j][33];
            float coef = dtv * xv;
            float y = 0.f;
#pragma unroll
            for (int n = 0; n < 16; n++) {
                hs[n] = fmaf(hs[n], dAv, coef * sBC[buf][j][n]);
                y = fmaf(hs[n], sBC[buf][j][16 + n], y);
            }
            P *= dAv;
            int s = s0 + gg * 8 + j;
            g_y[rowof(s) * (long)DI + h * HD + p] = fmaf(dp, xv, y);
            if (p == 0) g_P[(size_t)sid * LL + s] = P;
        }
        __syncthreads();
    }

    float* Sp = g_S + (size_t)blk * (HD * 16) + p * 16;
#pragma unroll
    for (int n = 0; n < 16; n++) Sp[n] = hs[n];
}

// ---------------- scan pass 2: chunk-state propagation, prefetched ----------------
__global__ __launch_bounds__(64)
void state_scan_k()
{
    int sid = blockIdx.x;
    int p = threadIdx.x;
    __shared__ float sP[16];
    if (p < 16) sP[p] = g_P[(size_t)sid * LL + p * CL + CL - 1];
    __syncthreads();

    size_t base = (size_t)sid * NC * (HD * 16) + p * 16;
    float hs[16], nxt[16];
#pragma unroll
    for (int n = 0; n < 16; n++) { hs[n] = 0.f; nxt[n] = g_S[base + n]; }

    for (int c = 0; c < NC; c++) {
        size_t off = base + (size_t)c * (HD * 16);
#pragma unroll
        for (int n = 0; n < 16; n++) g_hin[off + n] = hs[n];
        float cur[16];
#pragma unroll
        for (int n = 0; n < 16; n++) cur[n] = nxt[n];
        if (c + 1 < NC) {
            size_t off2 = off + HD * 16;
#pragma unroll
            for (int n = 0; n < 16; n++) nxt[n] = g_S[off2 + n];
        }
        float Pt = sP[c];
#pragma unroll
        for (int n = 0; n < 16; n++) hs[n] = fmaf(hs[n], Pt, cur[n]);
    }
}

// ---------------- scan pass 3: y[s] += P[s] * (C[s] . h_in) ----------------
__global__ __launch_bounds__(64)
void fixup_k()
{
    int blk = blockIdx.x;
    int cm  = blk % (NC - 1);
    int sid = blk / (NC - 1);
    int c   = cm + 1;
    int d = sid >> 7, b = (sid >> 4) & 7, h = sid & 15;
    int p = threadIdx.x;
    long base0 = (long)d * MT + (long)b * LL;

    size_t off = ((size_t)(sid * NC + c)) * (HD * 16) + p * 16;
    float hin[16];
#pragma unroll
    for (int n = 0; n < 16; n++) hin[n] = g_hin[off + n];

    __shared__ float sC[4][16];
    __shared__ float sP[4];
    int s0 = c * CL;

    for (int i = 0; i < CL; i += 4) {
        {
            int tsub = p >> 4, n = p & 15;
            int s = s0 + i + tsub;
            int t = (d == 0) ? s : (LL - 1 - s);
            sC[tsub][n] = g_xbc[(base0 + t) * (long)CD + DI + 16 + n];
            if (n == 0) sP[tsub] = g_P[(size_t)sid * LL + s];
        }
        __syncthreads();
        float av[4];
#pragma unroll
        for (int j = 0; j < 4; j++) {
            float y = 0.f;
#pragma unroll
            for (int n = 0; n < 16; n++) y = fmaf(hin[n], sC[j][n], y);
            av[j] = y;
        }
#pragma unroll
        for (int j = 0; j < 4; j++) {
            int s = s0 + i + j;
            int t = (d == 0) ? s : (LL - 1 - s);
            long row = base0 + t;
            g_y[row * (long)DI + h * HD + p] += sP[j] * av[j];
        }
        __syncthreads();
    }
}

// ---------------- gated RMSNorm (z from fp16, writes fp16 for gemm_out) ----------------
__global__ __launch_bounds__(256)
void gnorm_k(const float* __restrict__ nwF, const float* __restrict__ nwB)
{
    long r = blockIdx.x;
    int  d = (int)(r / MT);
    const float* nw = (d == 0) ? nwF : nwB;
    const float*  yp = g_y   + r * (long)DI;
    const __half* zp = g_zxh + r * (long)DIP;

    int i0 = threadIdx.x * 4;
    __half2 z01 = *(const __half2*)&zp[i0];
    __half2 z23 = *(const __half2*)&zp[i0 + 2];
    float zf[4] = { __low2float(z01), __high2float(z01),
                    __low2float(z23), __high2float(z23) };
    float v[4];
    float ss = 0.f;
#pragma unroll
    for (int j = 0; j < 4; j++) {
        float val = yp[i0 + j] * siluf(zf[j]);
        v[j] = val;
        ss = fmaf(val, val, ss);
    }
#pragma unroll
    for (int off = 16; off; off >>= 1) ss += __shfl_xor_sync(~0u, ss, off);
    __shared__ float ws[8];
    if ((threadIdx.x & 31) == 0) ws[threadIdx.x >> 5] = ss;
    __syncthreads();
    float tot = ws[0] + ws[1] + ws[2] + ws[3] + ws[4] + ws[5] + ws[6] + ws[7];
    float scale = rsqrtf(tot * (1.f / 1024.f) + 1e-5f);
    float o0 = v[0] * scale * nw[i0 + 0];
    float o1 = v[1] * scale * nw[i0 + 1];
    float o2 = v[2] * scale * nw[i0 + 2];
    float o3 = v[3] * scale * nw[i0 + 3];
    __half2* dst = (__half2*)&g_gh[r * (long)DI + i0];
    dst[0] = __floats2half2_rn(o0, o1);
    dst[1] = __floats2half2_rn(o2, o3);
}

// ---------------- launch ----------------
extern "C" void kernel_launch(void* const* d_in, const int* in_sizes, int n_in,
                              void* d_out, int out_size)
{
    const float* x    = (const float*)d_in[0];
    const float* ipwF = (const float*)d_in[1];
    const float* cwF  = (const float*)d_in[2];
    const float* cbF  = (const float*)d_in[3];
    const float* dbF  = (const float*)d_in[4];
    const float* alF  = (const float*)d_in[5];
    const float* dpF  = (const float*)d_in[6];
    const float* nwF  = (const float*)d_in[7];
    const float* opF  = (const float*)d_in[8];
    const float* ipwB = (const float*)d_in[9];
    const float* cwB  = (const float*)d_in[10];
    const float* cbB  = (const float*)d_in[11];
    const float* dbB  = (const float*)d_in[12];
    const float* alB  = (const float*)d_in[13];
    const float* dpB  = (const float*)d_in[14];
    const float* nwB  = (const float*)d_in[15];
    const float* opB  = (const float*)d_in[16];
    float* out = (float*)d_out;

    __half *zxh_d, *xh_d, *wih_d, *woh_d, *gh_d;
    cudaGetSymbolAddress((void**)&zxh_d, g_zxh);
    cudaGetSymbolAddress((void**)&xh_d,  g_xh);
    cudaGetSymbolAddress((void**)&wih_d, g_wih);
    cudaGetSymbolAddress((void**)&woh_d, g_woh);
    cudaGetSymbolAddress((void**)&gh_d,  g_gh);

    cudaFuncSetAttribute((const void*)gemm_in,
                         cudaFuncAttributeMaxDynamicSharedMemorySize, GEMM_SMEM);
    cudaFuncSetAttribute((const void*)gemm_out,
                         cudaFuncAttributeMaxDynamicSharedMemorySize, GEMM_SMEM);

    // 0) fp32 -> fp16 conversions (one launch, 5 regions)
    {
        int total = N4_X + 2 * N4_WI + 2 * N4_WO;
        tohalf_all<<<(total + 255) / 256, 256>>>(
            (const float4*)x, (const float4*)ipwF, (const float4*)ipwB,
            (const float4*)opF, (const float4*)opB,
            (__half2*)xh_d, (__half2*)wih_d, (__half2*)woh_d);
    }

    // 1) in_proj both directions + fused dadt tail blocks (x = 17), fp16 out
    gemm_in<<<dim3(18, 128, 2), 256, GEMM_SMEM>>>(
        xh_d, wih_d, wih_d + (size_t)DIP * DM, zxh_d,
        x, ipwF, ipwB, dbF, alF, dbB, alB);

    // 2) depthwise conv + silu (fp16 input)
    {
        long total = 2L * 8 * (LL / CTT) * CD;
        conv_silu_k<<<(unsigned)(total / 256), 256>>>(cwF, cbF, cwB, cbB);
    }

    // 3) chunked selective scan
    chunk_scan_k<<<NSCAN * NC, 64>>>(dpF, dpB);
    state_scan_k<<<NSCAN, 64>>>();
    fixup_k<<<NSCAN * (NC - 1), 64>>>();

    // 4) gated RMSNorm (fp16 z in, fp16 out)
    gnorm_k<<<2 * MT, 256>>>(nwF, nwB);

    // 5) out_proj: single fp16 GEMM, K-concat fwd+bwd
    gemm_out<<<dim3(4, 128), 256, GEMM_SMEM>>>(
        gh_d, gh_d + (size_t)MT * DI,
        woh_d, woh_d + (size_t)DM * DI, out);
}